// round 9
// baseline (speedup 1.0000x reference)
#include <cuda_runtime.h>
#include <cuda_fp16.h>
#include <math.h>
#include <stdint.h>

#define NN 30000
#define NNP 30080   // padded to multiple of 128
#define NE 480000
#define NB 4096
#define NSB 118

// ---------------- device scratch ----------------
__device__ __align__(16) __half g_cid[NNP * 896];
__device__ __align__(16) __half g_x1[NNP * 896];
__device__ __align__(16) __half g_x [NNP * 256];
__device__ __align__(16) __half g_h [NNP * 256];
__device__ __align__(16) __half g_hw[NNP * 256];   // GEMM out / gather in (fp16)
__device__ __align__(16) __half g_pc[NB * 256];    // pair out
__device__ __align__(16) __half g_f1[NB * 1024];   // f1 out
__device__ float g_f2[NB * 256];           // f2 out (feeds fp32 sgemm)
__device__ float g_f3[NB * 64];            // f3 out
__device__ float g_dinv[NN];
__device__ int   g_deg[NN];
__device__ int   g_cnt[NN];
__device__ int   g_rowptr[NN + 1];
__device__ int   g_col[NE];
__device__ float g_wgt[NE];
__device__ int   g_bsum[128];
__device__ int   g_boff[128];

// transposed fp16 weights (element offsets)
#define OFF_BB2 0                       // 896 x 896
#define OFF_BB3 (OFF_BB2 + 896*896)     // 256 x 896
#define OFF_G1  (OFF_BB3 + 256*896)     // 256 x 256
#define OFF_G2  (OFF_G1  + 256*256)
#define OFF_G3  (OFF_G2  + 256*256)
#define OFF_G4  (OFF_G3  + 256*256)    // 128 x 256
#define OFF_G5  (OFF_G4  + 128*256)    // 128 x 128
#define OFF_F1  (OFF_G5  + 128*128)    // 1024 x 256
#define OFF_F2  (OFF_F1  + 1024*256)   // 256 x 1024
#define WT_TOT  (OFF_F2  + 256*1024)
#define WT_ZERO (OFF_G1)               // zero-init BB2t + BB3t pad regions
__device__ __align__(16) __half g_wt[WT_TOT];

// ---------------- helpers ----------------
__device__ __forceinline__ uint32_t smem_u32(const void* p) {
    uint32_t a;
    asm("{ .reg .u64 t; cvta.to.shared.u64 t, %1; cvt.u32.u64 %0, t; }" : "=r"(a) : "l"(p));
    return a;
}
#define CP16(d, s) asm volatile("cp.async.cg.shared.global [%0], [%1], 16;" :: "r"(d), "l"(s) : "memory")
#define CPCOMMIT() asm volatile("cp.async.commit_group;" ::: "memory")
template<int W> __device__ __forceinline__ void cp_wait() {
    asm volatile("cp.async.wait_group %0;" :: "n"(W) : "memory");
}

// ---------------- graph preprocessing ----------------
__global__ void k_zero_deg() {
    int i = blockIdx.x * blockDim.x + threadIdx.x;
    if (i < NN) { g_deg[i] = 0; g_cnt[i] = 0; }
}
__global__ void k_count(const int* __restrict__ edges) {
    int e = blockIdx.x * blockDim.x + threadIdx.x;
    if (e < NE) atomicAdd(&g_deg[edges[NE + e]], 1);
}
__global__ void k_dinv() {
    int i = blockIdx.x * blockDim.x + threadIdx.x;
    if (i < NN) g_dinv[i] = rsqrtf((float)(g_deg[i] + 1));
}
__global__ void k_scanA() {
    __shared__ int sh[256];
    int tid = threadIdx.x;
    int i = blockIdx.x * 256 + tid;
    int v = (i < NN) ? g_deg[i] : 0;
    sh[tid] = v;
    __syncthreads();
#pragma unroll
    for (int off = 1; off < 256; off <<= 1) {
        int t = (tid >= off) ? sh[tid - off] : 0;
        __syncthreads();
        sh[tid] += t;
        __syncthreads();
    }
    if (i < NN) g_rowptr[i] = sh[tid] - v;
    if (tid == 255) g_bsum[blockIdx.x] = sh[255];
}
__global__ void k_scanB() {
    __shared__ int sh[128];
    int tid = threadIdx.x;
    int v = (tid < NSB) ? g_bsum[tid] : 0;
    sh[tid] = v;
    __syncthreads();
#pragma unroll
    for (int off = 1; off < 128; off <<= 1) {
        int t = (tid >= off) ? sh[tid - off] : 0;
        __syncthreads();
        sh[tid] += t;
        __syncthreads();
    }
    if (tid < NSB) g_boff[tid] = sh[tid] - v;
    if (tid == 127) g_rowptr[NN] = sh[127];
}
__global__ void k_scanC() {
    int i = blockIdx.x * 256 + threadIdx.x;
    if (i < NN) g_rowptr[i] += g_boff[blockIdx.x];
}
__global__ void k_fill(const int* __restrict__ edges) {
    int e = blockIdx.x * blockDim.x + threadIdx.x;
    if (e < NE) {
        int s = edges[e];
        int d = edges[NE + e];
        int pos = g_rowptr[d] + atomicAdd(&g_cnt[d], 1);
        g_col[pos] = s;
        g_wgt[pos] = g_dinv[s] * g_dinv[d];
    }
}

// ---------------- producers: pad + fp16-convert ----------------
__global__ void k_pad_cid(const float* __restrict__ cid) {
    int idx = blockIdx.x * 256 + threadIdx.x;
    if (idx >= NNP * 896) return;
    int row = idx / 896, col = idx - row * 896;
    g_cid[idx] = __float2half_rn((row < NN && col < 881) ? cid[(long)row * 881 + col] : 0.f);
}
__global__ void k_zero_wt() {
    int i = blockIdx.x * 256 + threadIdx.x;
    if (i < WT_ZERO) g_wt[i] = __float2half_rn(0.f);
}
// dst[c*dld + r] = fp16(src[r*C + c])
__global__ void k_transpose2(const float* __restrict__ src, __half* __restrict__ dst,
                             int R, int C, int dld) {
    __shared__ float t[32][33];
    int c0 = blockIdx.x * 32, r0 = blockIdx.y * 32;
    int x = threadIdx.x, y = threadIdx.y;  // 32 x 8
#pragma unroll
    for (int i = 0; i < 4; i++) {
        int r = r0 + y + i * 8;
        if (r < R && c0 + x < C) t[y + i * 8][x] = src[(long)r * C + c0 + x];
    }
    __syncthreads();
#pragma unroll
    for (int i = 0; i < 4; i++) {
        int c = c0 + y + i * 8;
        if (c < C && r0 + x < R) dst[(long)c * dld + r0 + x] = __float2half_rn(t[x][y + i * 8]);
    }
}

// ---------------- fp16 mma.sync GEMM, cp.async double-buffered ----------------
// C[M,N] = A[M,Kpad] @ Bt[N,Kpad]^T, fp16 operands, fp32 accum.
// EPI: 0 none, 1 relu+bias, 2 relu+softthr+bias. OUTH: 1 -> half output, 0 -> float.
#define SMSH 40   // smem row stride in halfs (32 data + 8 pad)
template <int EPI, int OUTH>
__global__ __launch_bounds__(256, 2) void k_hgemm(
    const __half* __restrict__ A, const __half* __restrict__ Bt,
    const float* __restrict__ bias, const float* __restrict__ thr_p,
    void* __restrict__ Cv, int M, int N, int Kpad, int lda, int ldb, int ldc, int fillw)
{
    __shared__ __align__(16) __half smA[2][128 * SMSH];
    __shared__ __align__(16) __half smB[2][128 * SMSH];
    int tid = threadIdx.x, wid = tid >> 5, lane = tid & 31;
    int row0 = blockIdx.y * 128, col0 = blockIdx.x * 128;
    int wr = wid >> 2, wc = wid & 3;     // warp grid 2 x 4, warp tile 64 x 32
    int q = lane >> 2, t4 = lane & 3;

    int r0 = tid >> 2, off = (tid & 3) * 8;   // off in halfs
    int r1 = r0 + 64;
    const __half* pA0 = A + (long)(row0 + r0) * lda + off;
    const __half* pA1 = A + (long)(row0 + r1) * lda + off;
    const __half* pB0 = Bt + (long)(col0 + r0) * ldb + off;
    const __half* pB1 = Bt + (long)(col0 + r1) * ldb + off;
    uint32_t aA = smem_u32(smA), aB = smem_u32(smB);
    uint32_t dA0 = aA + (r0 * SMSH + off) * 2;
    uint32_t dA1 = aA + (r1 * SMSH + off) * 2;
    uint32_t dB0 = aB + (r0 * SMSH + off) * 2;
    uint32_t dB1 = aB + (r1 * SMSH + off) * 2;
    const uint32_t SBo = 128 * SMSH * 2;

    float acc[16][4];
#pragma unroll
    for (int i = 0; i < 16; i++)
#pragma unroll
        for (int j = 0; j < 4; j++) acc[i][j] = 0.f;

    int nch = Kpad >> 5;    // 32-K chunks
    CP16(dA0, pA0); CP16(dA1, pA1); CP16(dB0, pB0); CP16(dB1, pB1);
    CPCOMMIT();

    int buf = 0;
    for (int ch = 0; ch < nch; ch++) {
        if (ch + 1 < nch) {
            int k0 = (ch + 1) << 5;
            uint32_t o = (buf ^ 1) ? SBo : 0u;
            CP16(dA0 + o, pA0 + k0); CP16(dA1 + o, pA1 + k0);
            CP16(dB0 + o, pB0 + k0); CP16(dB1 + o, pB1 + k0);
            CPCOMMIT();
            cp_wait<1>();
        } else {
            cp_wait<0>();
        }
        __syncthreads();
        const __half* SA = smA[buf];
        const __half* SB = smB[buf];
#pragma unroll
        for (int s = 0; s < 2; s++) {
            int koff = s * 16 + 2 * t4;
            uint32_t af[4][4], bf[4][2];
#pragma unroll
            for (int tm = 0; tm < 4; tm++) {
                int r = wr * 64 + tm * 16 + q;
                af[tm][0] = *(const uint32_t*)&SA[r * SMSH + koff];
                af[tm][1] = *(const uint32_t*)&SA[(r + 8) * SMSH + koff];
                af[tm][2] = *(const uint32_t*)&SA[r * SMSH + koff + 8];
                af[tm][3] = *(const uint32_t*)&SA[(r + 8) * SMSH + koff + 8];
            }
#pragma unroll
            for (int tn = 0; tn < 4; tn++) {
                int n = wc * 32 + tn * 8 + q;
                bf[tn][0] = *(const uint32_t*)&SB[n * SMSH + koff];
                bf[tn][1] = *(const uint32_t*)&SB[n * SMSH + koff + 8];
            }
#pragma unroll
            for (int tm = 0; tm < 4; tm++)
#pragma unroll
                for (int tn = 0; tn < 4; tn++) {
                    float* c = acc[tm * 4 + tn];
                    asm volatile(
                        "mma.sync.aligned.m16n8k16.row.col.f32.f16.f16.f32 "
                        "{%0,%1,%2,%3}, {%4,%5,%6,%7}, {%8,%9}, {%0,%1,%2,%3};"
                        : "+f"(c[0]), "+f"(c[1]), "+f"(c[2]), "+f"(c[3])
                        : "r"(af[tm][0]), "r"(af[tm][1]), "r"(af[tm][2]), "r"(af[tm][3]),
                          "r"(bf[tn][0]), "r"(bf[tn][1]));
                }
        }
        __syncthreads();
        buf ^= 1;
    }

    // epilogue
    float thr = (EPI == 2) ? thr_p[0] : 0.f;
#pragma unroll
    for (int tm = 0; tm < 4; tm++) {
#pragma unroll
        for (int half_ = 0; half_ < 2; half_++) {
            int gr = row0 + wr * 64 + tm * 16 + q + half_ * 8;
            if (gr >= M) continue;
#pragma unroll
            for (int tn = 0; tn < 4; tn++) {
#pragma unroll
                for (int cc = 0; cc < 2; cc++) {
                    int gc = col0 + wc * 32 + tn * 8 + 2 * t4 + cc;
                    if (gc >= fillw) continue;
                    float v = 0.f;
                    if (gc < N) {
                        v = acc[tm * 4 + tn][half_ * 2 + cc];
                        if (EPI != 0) v += bias[gc];
                        if (EPI == 1) v = fmaxf(v, 0.f);
                        if (EPI == 2) { v = fmaxf(v, 0.f); v = fmaxf(v - thr, 0.f); }
                    }
                    if (OUTH) ((__half*)Cv)[(long)gr * ldc + gc] = __float2half_rn(v);
                    else      ((float*)Cv)[(long)gr * ldc + gc] = v;
                }
            }
        }
    }
}

// ---------------- fp32 SGEMM (f3 tail layer) ----------------
#define BM 128
#define BN 128
#define BK 16
#define AP 132
template <int EPI>
__global__ __launch_bounds__(256, 2) void k_sgemm(
    const float* __restrict__ A, const float* __restrict__ B,
    const float* __restrict__ bias, const float* __restrict__ thr_p,
    float* __restrict__ C, int M, int N, int K)
{
    __shared__ float As[2][BK][AP];
    __shared__ float Bs[2][BK][BN];
    int tid = threadIdx.x;
    int row0 = blockIdx.y * BM, col0 = blockIdx.x * BN;
    int tx = tid & 15, ty = tid >> 4;
    int ar[8], ac[8], br[8], bc[8];
#pragma unroll
    for (int i = 0; i < 8; i++) {
        int idx = i * 256 + tid;
        ar[i] = idx >> 4;  ac[i] = idx & 15;
        br[i] = idx >> 7;  bc[i] = idx & 127;
    }
    float acc[8][8];
#pragma unroll
    for (int i = 0; i < 8; i++)
#pragma unroll
        for (int j = 0; j < 8; j++) acc[i][j] = 0.f;
    float ldA[8], ldB[8];
    int nt = (K + BK - 1) / BK;
#pragma unroll
    for (int i = 0; i < 8; i++) {
        int gr = row0 + ar[i], gc = ac[i];
        ldA[i] = (gr < M && gc < K) ? A[(long)gr * K + gc] : 0.f;
        int hr = br[i], hc = col0 + bc[i];
        ldB[i] = (hr < K && hc < N) ? B[(long)hr * N + hc] : 0.f;
    }
#pragma unroll
    for (int i = 0; i < 8; i++) { As[0][ac[i]][ar[i]] = ldA[i]; Bs[0][br[i]][bc[i]] = ldB[i]; }
    __syncthreads();
    int cur = 0;
    for (int t = 0; t < nt; t++) {
        int kn = (t + 1) * BK;
        if (t + 1 < nt) {
#pragma unroll
            for (int i = 0; i < 8; i++) {
                int gr = row0 + ar[i], gc = kn + ac[i];
                ldA[i] = (gr < M && gc < K) ? A[(long)gr * K + gc] : 0.f;
                int hr = kn + br[i], hc = col0 + bc[i];
                ldB[i] = (hr < K && hc < N) ? B[(long)hr * N + hc] : 0.f;
            }
        }
#pragma unroll
        for (int kk = 0; kk < BK; kk++) {
            float4 a0 = *(const float4*)&As[cur][kk][ty * 8];
            float4 a1 = *(const float4*)&As[cur][kk][ty * 8 + 4];
            float4 b0 = *(const float4*)&Bs[cur][kk][tx * 8];
            float4 b1 = *(const float4*)&Bs[cur][kk][tx * 8 + 4];
            float ra[8] = {a0.x, a0.y, a0.z, a0.w, a1.x, a1.y, a1.z, a1.w};
            float rb[8] = {b0.x, b0.y, b0.z, b0.w, b1.x, b1.y, b1.z, b1.w};
#pragma unroll
            for (int i = 0; i < 8; i++)
#pragma unroll
                for (int j = 0; j < 8; j++) acc[i][j] = fmaf(ra[i], rb[j], acc[i][j]);
        }
        if (t + 1 < nt) {
            int nxt = cur ^ 1;
#pragma unroll
            for (int i = 0; i < 8; i++) { As[nxt][ac[i]][ar[i]] = ldA[i]; Bs[nxt][br[i]][bc[i]] = ldB[i]; }
            __syncthreads();
            cur = nxt;
        }
    }
    float thr = (EPI == 2) ? thr_p[0] : 0.f;
#pragma unroll
    for (int i = 0; i < 8; i++) {
        int gr = row0 + ty * 8 + i;
        if (gr >= M) continue;
#pragma unroll
        for (int j = 0; j < 8; j++) {
            int gc = col0 + tx * 8 + j;
            if (gc >= N) continue;
            float v = acc[i][j] + (bias ? bias[gc] : 0.f);
            if (EPI == 1) v = fmaxf(v, 0.f);
            if (EPI == 2) { v = fmaxf(v, 0.f); v = fmaxf(v - thr, 0.f); }
            C[(long)gr * N + gc] = v;
        }
    }
}

// ---------------- GCN gather: fp16 in (hw), fp16 out ----------------
// Each thread owns 8 features (one 16B uint4). blockDim = (F/8, nodes/blk)
__device__ __forceinline__ void h8_fma(float* a, uint4 v, float w) {
    __half2* h = (__half2*)&v;
#pragma unroll
    for (int j = 0; j < 4; j++) {
        float2 f = __half22float2(h[j]);
        a[2 * j]     += w * f.x;
        a[2 * j + 1] += w * f.y;
    }
}
template <int F>
__global__ void k_gather_h(const __half* __restrict__ hw, const float* __restrict__ bias,
                           __half* __restrict__ out)
{
    int n = blockIdx.x * blockDim.y + threadIdx.y;
    if (n >= NN) return;
    int f8 = threadIdx.x;            // group of 8 features
    const int Fg = F / 8;
    const uint4* __restrict__ hw4 = (const uint4*)hw;
    float d = g_dinv[n];
    float c = d * d;
    float acc[8] = {0, 0, 0, 0, 0, 0, 0, 0};
    h8_fma(acc, hw4[(long)n * Fg + f8], c);   // self loop
    int s = g_rowptr[n], e = g_rowptr[n + 1];
    int i = s;
    for (; i + 4 <= e; i += 4) {
        int   c0 = g_col[i],  c1 = g_col[i + 1], c2 = g_col[i + 2], c3 = g_col[i + 3];
        float w0 = g_wgt[i],  w1 = g_wgt[i + 1], w2 = g_wgt[i + 2], w3 = g_wgt[i + 3];
        uint4 v0 = hw4[(long)c0 * Fg + f8];
        uint4 v1 = hw4[(long)c1 * Fg + f8];
        uint4 v2 = hw4[(long)c2 * Fg + f8];
        uint4 v3 = hw4[(long)c3 * Fg + f8];
        h8_fma(acc, v0, w0); h8_fma(acc, v1, w1);
        h8_fma(acc, v2, w2); h8_fma(acc, v3, w3);
    }
    for (; i < e; i++) {
        uint4 v0 = hw4[(long)g_col[i] * Fg + f8];
        h8_fma(acc, v0, g_wgt[i]);
    }
    const float4* b4 = (const float4*)(bias + f8 * 8);
    float4 b0 = b4[0], b1 = b4[1];
    float bb[8] = {b0.x, b0.y, b0.z, b0.w, b1.x, b1.y, b1.z, b1.w};
    uint4 o;
    __half2* oh = (__half2*)&o;
#pragma unroll
    for (int j = 0; j < 4; j++) {
        float v0 = acc[2 * j] + bb[2 * j];
        float v1 = acc[2 * j + 1] + bb[2 * j + 1];
        v0 = v0 > 0.f ? v0 : expm1f(v0);
        v1 = v1 > 0.f ? v1 : expm1f(v1);
        oh[j] = __floats2half2_rn(v0, v1);
    }
    ((uint4*)out)[(long)n * Fg + f8] = o;
}

// ---------------- pair readout: fp16 in/out ----------------
__global__ void k_pair(const __half* __restrict__ h,
                       const int* __restrict__ i1, const int* __restrict__ i2,
                       __half* __restrict__ xc)
{
    int p = blockIdx.x;
    int f = threadIdx.x;
    float v = (f < 128) ? __half2float(h[(long)i1[p] * 128 + f])
                        : __half2float(h[(long)i2[p] * 128 + (f - 128)]);
    __shared__ float red[256];
    red[f] = v * v;
    __syncthreads();
    for (int off = 128; off > 0; off >>= 1) {
        if (f < off) red[f] += red[f + off];
        __syncthreads();
    }
    float norm = fmaxf(sqrtf(red[0]), 1e-12f);
    xc[(long)p * 256 + f] = __float2half_rn(v / norm);
}

__global__ void k_out(const float* __restrict__ x, const float* __restrict__ W,
                      const float* __restrict__ b, float* __restrict__ out)
{
    int idx = blockIdx.x * blockDim.x + threadIdx.x;
    if (idx >= NB * 2) return;
    int p = idx >> 1, c = idx & 1;
    float acc = b[c];
#pragma unroll
    for (int k = 0; k < 64; k++) acc += x[p * 64 + k] * W[k * 2 + c];
    out[idx] = acc;
}

// ---------------- launch ----------------
extern "C" void kernel_launch(void* const* d_in, const int* in_sizes, int n_in,
                              void* d_out, int out_size)
{
    const float* cid   = (const float*)d_in[0];
    const int*   edges = (const int*)  d_in[1];
    const int*   i1    = (const int*)  d_in[2];
    const int*   i2    = (const int*)  d_in[3];
    const float* thr   = (const float*)d_in[4];
    const float* bb2W  = (const float*)d_in[5];  const float* bb2b = (const float*)d_in[6];
    const float* bb3W  = (const float*)d_in[7];  const float* bb3b = (const float*)d_in[8];
    const float* g1W   = (const float*)d_in[9];  const float* g1b  = (const float*)d_in[10];
    const float* g2W   = (const float*)d_in[11]; const float* g2b  = (const float*)d_in[12];
    const float* g3W   = (const float*)d_in[13]; const float* g3b  = (const float*)d_in[14];
    const float* g4W   = (const float*)d_in[15]; const float* g4b  = (const float*)d_in[16];
    const float* g5W   = (const float*)d_in[17]; const float* g5b  = (const float*)d_in[18];
    const float* f1W   = (const float*)d_in[19]; const float* f1b  = (const float*)d_in[20];
    const float* f2W   = (const float*)d_in[21]; const float* f2b  = (const float*)d_in[22];
    const float* f3W   = (const float*)d_in[23]; const float* f3b  = (const float*)d_in[24];
    const float* oW    = (const float*)d_in[25]; const float* ob   = (const float*)d_in[26];

    void *pcid, *px1, *px, *ph, *phw, *ppc, *pf1, *pf2, *pf3, *pwt;
    cudaGetSymbolAddress(&pcid, g_cid);
    cudaGetSymbolAddress(&px1,  g_x1);
    cudaGetSymbolAddress(&px,   g_x);
    cudaGetSymbolAddress(&ph,   g_h);
    cudaGetSymbolAddress(&phw,  g_hw);
    cudaGetSymbolAddress(&ppc,  g_pc);
    cudaGetSymbolAddress(&pf1,  g_f1);
    cudaGetSymbolAddress(&pf2,  g_f2);
    cudaGetSymbolAddress(&pf3,  g_f3);
    cudaGetSymbolAddress(&pwt,  g_wt);
    __half* cidp = (__half*)pcid;
    __half* x1   = (__half*)px1;
    __half* x    = (__half*)px;
    __half* h    = (__half*)ph;
    __half* hw   = (__half*)phw;
    __half* pc   = (__half*)ppc;
    __half* f1o  = (__half*)pf1;
    float*  f2o  = (float*)pf2;
    float*  f3o  = (float*)pf3;
    __half* wt   = (__half*)pwt;

    // graph preprocessing
    k_zero_deg<<<(NN + 255) / 256, 256>>>();
    k_count<<<(NE + 255) / 256, 256>>>(edges);
    k_dinv<<<(NN + 255) / 256, 256>>>();
    k_scanA<<<NSB, 256>>>();
    k_scanB<<<1, 128>>>();
    k_scanC<<<NSB, 256>>>();
    k_fill<<<(NE + 255) / 256, 256>>>(edges);

    // producers: fp16 padded input + transposed fp16 weights
    k_pad_cid<<<(NNP * 896 + 255) / 256, 256>>>(cid);
    k_zero_wt<<<(WT_ZERO + 255) / 256, 256>>>();
    dim3 tb(32, 8);
    k_transpose2<<<dim3(28, 28), tb>>>(bb2W, wt + OFF_BB2, 881, 881, 896);
    k_transpose2<<<dim3(8, 28),  tb>>>(bb3W, wt + OFF_BB3, 881, 256, 896);
    k_transpose2<<<dim3(8, 8),   tb>>>(g1W,  wt + OFF_G1,  256, 256, 256);
    k_transpose2<<<dim3(8, 8),   tb>>>(g2W,  wt + OFF_G2,  256, 256, 256);
    k_transpose2<<<dim3(8, 8),   tb>>>(g3W,  wt + OFF_G3,  256, 256, 256);
    k_transpose2<<<dim3(4, 8),   tb>>>(g4W,  wt + OFF_G4,  256, 128, 256);
    k_transpose2<<<dim3(4, 4),   tb>>>(g5W,  wt + OFF_G5,  128, 128, 128);
    k_transpose2<<<dim3(32, 8),  tb>>>(f1W,  wt + OFF_F1,  256, 1024, 256);
    k_transpose2<<<dim3(8, 32),  tb>>>(f2W,  wt + OFF_F2,  1024, 256, 1024);

    int MY = NNP / 128;  // 235

    // BasicBlock
    k_hgemm<2,1><<<dim3(7, MY), 256>>>(cidp, wt + OFF_BB2, bb2b, thr, x1,
                                       NN, 881, 896, 896, 896, 896, 896);
    k_hgemm<1,1><<<dim3(2, MY), 256>>>(x1, wt + OFF_BB3, bb3b, nullptr, x,
                                       NN, 256, 896, 896, 896, 256, 256);

    // GCN layers (GEMM -> fp16 hw -> gather)
    dim3 gat256(32, 8), gat128(16, 16);
    int ngb256 = (NN + 7) / 8, ngb128 = (NN + 15) / 16;
    k_hgemm<0,1><<<dim3(2, MY), 256>>>(x, wt + OFF_G1, nullptr, nullptr, hw,
                                       NN, 256, 256, 256, 256, 256, 256);
    k_gather_h<256><<<ngb256, gat256>>>(hw, g1b, h);
    k_hgemm<0,1><<<dim3(2, MY), 256>>>(h, wt + OFF_G2, nullptr, nullptr, hw,
                                       NN, 256, 256, 256, 256, 256, 256);
    k_gather_h<256><<<ngb256, gat256>>>(hw, g2b, x);
    k_hgemm<0,1><<<dim3(2, MY), 256>>>(x, wt + OFF_G3, nullptr, nullptr, hw,
                                       NN, 256, 256, 256, 256, 256, 256);
    k_gather_h<256><<<ngb256, gat256>>>(hw, g3b, h);
    k_hgemm<0,1><<<dim3(1, MY), 256>>>(h, wt + OFF_G4, nullptr, nullptr, hw,
                                       NN, 128, 256, 256, 256, 128, 128);
    k_gather_h<128><<<ngb128, gat128>>>(hw, g4b, x);
    k_hgemm<0,1><<<dim3(1, MY), 256>>>(x, wt + OFF_G5, nullptr, nullptr, hw,
                                       NN, 128, 128, 128, 128, 128, 128);
    k_gather_h<128><<<ngb128, gat128>>>(hw, g5b, h);

    // pair readout
    k_pair<<<NB, 256>>>(h, i1, i2, pc);
    k_hgemm<1,1><<<dim3(8, 32), 256>>>(pc,  wt + OFF_F1, f1b, nullptr, f1o,
                                       NB, 1024, 256, 256, 256, 1024, 1024);
    k_hgemm<1,0><<<dim3(2, 32), 256>>>(f1o, wt + OFF_F2, f2b, nullptr, f2o,
                                       NB, 256, 1024, 1024, 1024, 256, 256);
    k_sgemm<1><<<dim3(1, 32), 256>>>(f2o, f3W, f3b, nullptr, f3o, NB, 64, 256);
    k_out<<<(NB * 2 + 255) / 256, 256>>>(f3o, oW, ob, (float*)d_out);
}

// round 10
// speedup vs baseline: 1.0186x; 1.0186x over previous
#include <cuda_runtime.h>
#include <cuda_fp16.h>
#include <math.h>
#include <stdint.h>

#define NN 30000
#define NNP 30080   // padded to multiple of 128
#define NE 480000
#define NB 4096
#define NSB 118

// ---------------- device scratch ----------------
__device__ __align__(16) __half g_cid[NNP * 896];
__device__ __align__(16) __half g_x1[NNP * 896];
__device__ __align__(16) __half g_x [NNP * 256];
__device__ __align__(16) __half g_h [NNP * 256];
__device__ float g_hw[NNP * 256];          // GEMM out / gather in (fp32)
__device__ __align__(16) __half g_pc[NB * 256];    // pair out
__device__ __align__(16) __half g_f1[NB * 1024];   // f1 out
__device__ float g_f2[NB * 256];           // f2 out (feeds fp32 sgemm)
__device__ float g_f3[NB * 64];            // f3 out
__device__ float g_dinv[NN];
__device__ int   g_deg[NN];
__device__ int   g_cnt[NN];
__device__ int   g_rowptr[NN + 1];
__device__ int   g_col[NE];
__device__ float g_wgt[NE];
__device__ int   g_bsum[128];
__device__ int   g_boff[128];

// transposed fp16 weights (element offsets)
#define OFF_BB2 0                       // 896 x 896
#define OFF_BB3 (OFF_BB2 + 896*896)     // 256 x 896
#define OFF_G1  (OFF_BB3 + 256*896)     // 256 x 256
#define OFF_G2  (OFF_G1  + 256*256)
#define OFF_G3  (OFF_G2  + 256*256)
#define OFF_G4  (OFF_G3  + 256*256)    // 128 x 256
#define OFF_G5  (OFF_G4  + 128*256)    // 128 x 128
#define OFF_F1  (OFF_G5  + 128*128)    // 1024 x 256
#define OFF_F2  (OFF_F1  + 1024*256)   // 256 x 1024
#define WT_TOT  (OFF_F2  + 256*1024)
#define WT_ZERO (OFF_G1)               // zero-init BB2t + BB3t pad regions
__device__ __align__(16) __half g_wt[WT_TOT];

// ---------------- helpers ----------------
__device__ __forceinline__ uint32_t smem_u32(const void* p) {
    uint32_t a;
    asm("{ .reg .u64 t; cvta.to.shared.u64 t, %1; cvt.u32.u64 %0, t; }" : "=r"(a) : "l"(p));
    return a;
}
#define CP16(d, s) asm volatile("cp.async.cg.shared.global [%0], [%1], 16;" :: "r"(d), "l"(s) : "memory")
#define CPCOMMIT() asm volatile("cp.async.commit_group;" ::: "memory")
template<int W> __device__ __forceinline__ void cp_wait() {
    asm volatile("cp.async.wait_group %0;" :: "n"(W) : "memory");
}

// ---------------- graph preprocessing ----------------
__global__ void k_zero_deg() {
    int i = blockIdx.x * blockDim.x + threadIdx.x;
    if (i < NN) { g_deg[i] = 0; g_cnt[i] = 0; }
}
__global__ void k_count(const int* __restrict__ edges) {
    int e = blockIdx.x * blockDim.x + threadIdx.x;
    if (e < NE) atomicAdd(&g_deg[edges[NE + e]], 1);
}
__global__ void k_dinv() {
    int i = blockIdx.x * blockDim.x + threadIdx.x;
    if (i < NN) g_dinv[i] = rsqrtf((float)(g_deg[i] + 1));
}
__global__ void k_scanA() {
    __shared__ int sh[256];
    int tid = threadIdx.x;
    int i = blockIdx.x * 256 + tid;
    int v = (i < NN) ? g_deg[i] : 0;
    sh[tid] = v;
    __syncthreads();
#pragma unroll
    for (int off = 1; off < 256; off <<= 1) {
        int t = (tid >= off) ? sh[tid - off] : 0;
        __syncthreads();
        sh[tid] += t;
        __syncthreads();
    }
    if (i < NN) g_rowptr[i] = sh[tid] - v;
    if (tid == 255) g_bsum[blockIdx.x] = sh[255];
}
__global__ void k_scanB() {
    __shared__ int sh[128];
    int tid = threadIdx.x;
    int v = (tid < NSB) ? g_bsum[tid] : 0;
    sh[tid] = v;
    __syncthreads();
#pragma unroll
    for (int off = 1; off < 128; off <<= 1) {
        int t = (tid >= off) ? sh[tid - off] : 0;
        __syncthreads();
        sh[tid] += t;
        __syncthreads();
    }
    if (tid < NSB) g_boff[tid] = sh[tid] - v;
    if (tid == 127) g_rowptr[NN] = sh[127];
}
__global__ void k_scanC() {
    int i = blockIdx.x * 256 + threadIdx.x;
    if (i < NN) g_rowptr[i] += g_boff[blockIdx.x];
}
__global__ void k_fill(const int* __restrict__ edges) {
    int e = blockIdx.x * blockDim.x + threadIdx.x;
    if (e < NE) {
        int s = edges[e];
        int d = edges[NE + e];
        int pos = g_rowptr[d] + atomicAdd(&g_cnt[d], 1);
        g_col[pos] = s;
        g_wgt[pos] = g_dinv[s] * g_dinv[d];
    }
}

// ---------------- producers: pad + fp16-convert ----------------
__global__ void k_pad_cid(const float* __restrict__ cid) {
    int idx = blockIdx.x * 256 + threadIdx.x;
    if (idx >= NNP * 896) return;
    int row = idx / 896, col = idx - row * 896;
    g_cid[idx] = __float2half_rn((row < NN && col < 881) ? cid[(long)row * 881 + col] : 0.f);
}
__global__ void k_zero_wt() {
    int i = blockIdx.x * 256 + threadIdx.x;
    if (i < WT_ZERO) g_wt[i] = __float2half_rn(0.f);
}
// dst[c*dld + r] = fp16(src[r*C + c])
__global__ void k_transpose2(const float* __restrict__ src, __half* __restrict__ dst,
                             int R, int C, int dld) {
    __shared__ float t[32][33];
    int c0 = blockIdx.x * 32, r0 = blockIdx.y * 32;
    int x = threadIdx.x, y = threadIdx.y;  // 32 x 8
#pragma unroll
    for (int i = 0; i < 4; i++) {
        int r = r0 + y + i * 8;
        if (r < R && c0 + x < C) t[y + i * 8][x] = src[(long)r * C + c0 + x];
    }
    __syncthreads();
#pragma unroll
    for (int i = 0; i < 4; i++) {
        int c = c0 + y + i * 8;
        if (c < C && r0 + x < R) dst[(long)c * dld + r0 + x] = __float2half_rn(t[x][y + i * 8]);
    }
}

// ---------------- fp16 mma.sync GEMM, cp.async 3-stage pipeline ------------
// C[M,N] = A[M,Kpad] @ Bt[N,Kpad]^T, fp16 operands, fp32 accum.
// EPI: 0 none, 1 relu+bias, 2 relu+softthr+bias. OUTH: 1 -> half out, 0 -> float.
// Requires Kpad multiple of 32 and Kpad >= 64 (nch >= 2).
#define SMSH 40   // smem row stride in halfs (32 data + 8 pad)
#define HG_STAGE (128 * SMSH)              // halfs per operand per stage
#define HG_SMEM  (3 * HG_STAGE * 2 * 2)    // bytes: 3 stages x (A+B)
template <int EPI, int OUTH>
__global__ __launch_bounds__(256, 2) void k_hgemm(
    const __half* __restrict__ A, const __half* __restrict__ Bt,
    const float* __restrict__ bias, const float* __restrict__ thr_p,
    void* __restrict__ Cv, int M, int N, int Kpad, int lda, int ldb, int ldc, int fillw)
{
    extern __shared__ __align__(16) __half sm[];
    __half* smA = sm;                      // 3 x HG_STAGE
    __half* smB = sm + 3 * HG_STAGE;       // 3 x HG_STAGE
    int tid = threadIdx.x, wid = tid >> 5, lane = tid & 31;
    int row0 = blockIdx.y * 128, col0 = blockIdx.x * 128;
    int wr = wid >> 2, wc = wid & 3;       // warp grid 2 x 4, warp tile 64 x 32
    int q = lane >> 2, t4 = lane & 3;

    int r0 = tid >> 2, off = (tid & 3) * 8;   // off in halfs
    int r1 = r0 + 64;
    const __half* pA0 = A + (long)(row0 + r0) * lda + off;
    const __half* pA1 = A + (long)(row0 + r1) * lda + off;
    const __half* pB0 = Bt + (long)(col0 + r0) * ldb + off;
    const __half* pB1 = Bt + (long)(col0 + r1) * ldb + off;
    uint32_t aA = smem_u32(smA), aB = smem_u32(smB);
    uint32_t dA0 = aA + (r0 * SMSH + off) * 2;
    uint32_t dA1 = aA + (r1 * SMSH + off) * 2;
    uint32_t dB0 = aB + (r0 * SMSH + off) * 2;
    uint32_t dB1 = aB + (r1 * SMSH + off) * 2;
    const uint32_t STo = HG_STAGE * 2;     // per-stage bytes

    float acc[16][4];
#pragma unroll
    for (int i = 0; i < 16; i++)
#pragma unroll
        for (int j = 0; j < 4; j++) acc[i][j] = 0.f;

    int nch = Kpad >> 5;    // 32-K chunks (nch >= 2 by contract)
    // prologue: stages 0 and 1
    CP16(dA0, pA0); CP16(dA1, pA1); CP16(dB0, pB0); CP16(dB1, pB1);
    CPCOMMIT();
    {
        int k0 = 32;
        CP16(dA0 + STo, pA0 + k0); CP16(dA1 + STo, pA1 + k0);
        CP16(dB0 + STo, pB0 + k0); CP16(dB1 + STo, pB1 + k0);
        CPCOMMIT();
    }

    for (int ch = 0; ch < nch; ch++) {
        if (ch + 2 < nch) {
            int k0 = (ch + 2) << 5;
            uint32_t o = ((ch + 2) % 3) * STo;
            CP16(dA0 + o, pA0 + k0); CP16(dA1 + o, pA1 + k0);
            CP16(dB0 + o, pB0 + k0); CP16(dB1 + o, pB1 + k0);
            CPCOMMIT();
            cp_wait<2>();
        } else if (ch + 1 < nch) {
            cp_wait<1>();
        } else {
            cp_wait<0>();
        }
        __syncthreads();
        const __half* SA = smA + (ch % 3) * HG_STAGE;
        const __half* SB = smB + (ch % 3) * HG_STAGE;
#pragma unroll
        for (int s = 0; s < 2; s++) {
            int koff = s * 16 + 2 * t4;
            uint32_t af[4][4], bf[4][2];
#pragma unroll
            for (int tm = 0; tm < 4; tm++) {
                int r = wr * 64 + tm * 16 + q;
                af[tm][0] = *(const uint32_t*)&SA[r * SMSH + koff];
                af[tm][1] = *(const uint32_t*)&SA[(r + 8) * SMSH + koff];
                af[tm][2] = *(const uint32_t*)&SA[r * SMSH + koff + 8];
                af[tm][3] = *(const uint32_t*)&SA[(r + 8) * SMSH + koff + 8];
            }
#pragma unroll
            for (int tn = 0; tn < 4; tn++) {
                int n = wc * 32 + tn * 8 + q;
                bf[tn][0] = *(const uint32_t*)&SB[n * SMSH + koff];
                bf[tn][1] = *(const uint32_t*)&SB[n * SMSH + koff + 8];
            }
#pragma unroll
            for (int tm = 0; tm < 4; tm++)
#pragma unroll
                for (int tn = 0; tn < 4; tn++) {
                    float* c = acc[tm * 4 + tn];
                    asm volatile(
                        "mma.sync.aligned.m16n8k16.row.col.f32.f16.f16.f32 "
                        "{%0,%1,%2,%3}, {%4,%5,%6,%7}, {%8,%9}, {%0,%1,%2,%3};"
                        : "+f"(c[0]), "+f"(c[1]), "+f"(c[2]), "+f"(c[3])
                        : "r"(af[tm][0]), "r"(af[tm][1]), "r"(af[tm][2]), "r"(af[tm][3]),
                          "r"(bf[tn][0]), "r"(bf[tn][1]));
                }
        }
        __syncthreads();
    }

    // epilogue
    float thr = (EPI == 2) ? thr_p[0] : 0.f;
#pragma unroll
    for (int tm = 0; tm < 4; tm++) {
#pragma unroll
        for (int half_ = 0; half_ < 2; half_++) {
            int gr = row0 + wr * 64 + tm * 16 + q + half_ * 8;
            if (gr >= M) continue;
#pragma unroll
            for (int tn = 0; tn < 4; tn++) {
#pragma unroll
                for (int cc = 0; cc < 2; cc++) {
                    int gc = col0 + wc * 32 + tn * 8 + 2 * t4 + cc;
                    if (gc >= fillw) continue;
                    float v = 0.f;
                    if (gc < N) {
                        v = acc[tm * 4 + tn][half_ * 2 + cc];
                        if (EPI != 0) v += bias[gc];
                        if (EPI == 1) v = fmaxf(v, 0.f);
                        if (EPI == 2) { v = fmaxf(v, 0.f); v = fmaxf(v - thr, 0.f); }
                    }
                    if (OUTH) ((__half*)Cv)[(long)gr * ldc + gc] = __float2half_rn(v);
                    else      ((float*)Cv)[(long)gr * ldc + gc] = v;
                }
            }
        }
    }
}

// ---------------- fp32 SGEMM (f3 tail layer) ----------------
#define BM 128
#define BN 128
#define BK 16
#define AP 132
template <int EPI>
__global__ __launch_bounds__(256, 2) void k_sgemm(
    const float* __restrict__ A, const float* __restrict__ B,
    const float* __restrict__ bias, const float* __restrict__ thr_p,
    float* __restrict__ C, int M, int N, int K)
{
    __shared__ float As[2][BK][AP];
    __shared__ float Bs[2][BK][BN];
    int tid = threadIdx.x;
    int row0 = blockIdx.y * BM, col0 = blockIdx.x * BN;
    int tx = tid & 15, ty = tid >> 4;
    int ar[8], ac[8], br[8], bc[8];
#pragma unroll
    for (int i = 0; i < 8; i++) {
        int idx = i * 256 + tid;
        ar[i] = idx >> 4;  ac[i] = idx & 15;
        br[i] = idx >> 7;  bc[i] = idx & 127;
    }
    float acc[8][8];
#pragma unroll
    for (int i = 0; i < 8; i++)
#pragma unroll
        for (int j = 0; j < 8; j++) acc[i][j] = 0.f;
    float ldA[8], ldB[8];
    int nt = (K + BK - 1) / BK;
#pragma unroll
    for (int i = 0; i < 8; i++) {
        int gr = row0 + ar[i], gc = ac[i];
        ldA[i] = (gr < M && gc < K) ? A[(long)gr * K + gc] : 0.f;
        int hr = br[i], hc = col0 + bc[i];
        ldB[i] = (hr < K && hc < N) ? B[(long)hr * N + hc] : 0.f;
    }
#pragma unroll
    for (int i = 0; i < 8; i++) { As[0][ac[i]][ar[i]] = ldA[i]; Bs[0][br[i]][bc[i]] = ldB[i]; }
    __syncthreads();
    int cur = 0;
    for (int t = 0; t < nt; t++) {
        int kn = (t + 1) * BK;
        if (t + 1 < nt) {
#pragma unroll
            for (int i = 0; i < 8; i++) {
                int gr = row0 + ar[i], gc = kn + ac[i];
                ldA[i] = (gr < M && gc < K) ? A[(long)gr * K + gc] : 0.f;
                int hr = kn + br[i], hc = col0 + bc[i];
                ldB[i] = (hr < K && hc < N) ? B[(long)hr * N + hc] : 0.f;
            }
        }
#pragma unroll
        for (int kk = 0; kk < BK; kk++) {
            float4 a0 = *(const float4*)&As[cur][kk][ty * 8];
            float4 a1 = *(const float4*)&As[cur][kk][ty * 8 + 4];
            float4 b0 = *(const float4*)&Bs[cur][kk][tx * 8];
            float4 b1 = *(const float4*)&Bs[cur][kk][tx * 8 + 4];
            float ra[8] = {a0.x, a0.y, a0.z, a0.w, a1.x, a1.y, a1.z, a1.w};
            float rb[8] = {b0.x, b0.y, b0.z, b0.w, b1.x, b1.y, b1.z, b1.w};
#pragma unroll
            for (int i = 0; i < 8; i++)
#pragma unroll
                for (int j = 0; j < 8; j++) acc[i][j] = fmaf(ra[i], rb[j], acc[i][j]);
        }
        if (t + 1 < nt) {
            int nxt = cur ^ 1;
#pragma unroll
            for (int i = 0; i < 8; i++) { As[nxt][ac[i]][ar[i]] = ldA[i]; Bs[nxt][br[i]][bc[i]] = ldB[i]; }
            __syncthreads();
            cur = nxt;
        }
    }
    float thr = (EPI == 2) ? thr_p[0] : 0.f;
#pragma unroll
    for (int i = 0; i < 8; i++) {
        int gr = row0 + ty * 8 + i;
        if (gr >= M) continue;
#pragma unroll
        for (int j = 0; j < 8; j++) {
            int gc = col0 + tx * 8 + j;
            if (gc >= N) continue;
            float v = acc[i][j] + (bias ? bias[gc] : 0.f);
            if (EPI == 1) v = fmaxf(v, 0.f);
            if (EPI == 2) { v = fmaxf(v, 0.f); v = fmaxf(v - thr, 0.f); }
            C[(long)gr * N + gc] = v;
        }
    }
}

// ---------------- GCN gather: fp32 in (hw), fp16 out (next GEMM A) ---------
__global__ void k_gather(const float* __restrict__ hw, const float* __restrict__ bias,
                         __half* __restrict__ out, int F)
{
    int n = blockIdx.x * 4 + threadIdx.y;
    if (n >= NN) return;
    int f4 = threadIdx.x;
    int Fq = F >> 2;
    const float4* __restrict__ hw4 = (const float4*)hw;
    float d = g_dinv[n];
    float c = d * d;
    float4 sv = hw4[(long)n * Fq + f4];
    float ax = sv.x * c, ay = sv.y * c, az = sv.z * c, aw = sv.w * c;
    int s = g_rowptr[n], e = g_rowptr[n + 1];
    int i = s;
    for (; i + 4 <= e; i += 4) {
        int   c0 = g_col[i],  c1 = g_col[i + 1], c2 = g_col[i + 2], c3 = g_col[i + 3];
        float w0 = g_wgt[i],  w1 = g_wgt[i + 1], w2 = g_wgt[i + 2], w3 = g_wgt[i + 3];
        float4 v0 = hw4[(long)c0 * Fq + f4];
        float4 v1 = hw4[(long)c1 * Fq + f4];
        float4 v2 = hw4[(long)c2 * Fq + f4];
        float4 v3 = hw4[(long)c3 * Fq + f4];
        ax += w0 * v0.x + w1 * v1.x + w2 * v2.x + w3 * v3.x;
        ay += w0 * v0.y + w1 * v1.y + w2 * v2.y + w3 * v3.y;
        az += w0 * v0.z + w1 * v1.z + w2 * v2.z + w3 * v3.z;
        aw += w0 * v0.w + w1 * v1.w + w2 * v2.w + w3 * v3.w;
    }
    for (; i < e; i++) {
        int c0 = g_col[i]; float w0 = g_wgt[i];
        float4 v0 = hw4[(long)c0 * Fq + f4];
        ax += w0 * v0.x; ay += w0 * v0.y; az += w0 * v0.z; aw += w0 * v0.w;
    }
    float4 b = ((const float4*)bias)[f4];
    ax += b.x; ay += b.y; az += b.z; aw += b.w;
    ax = ax > 0.f ? ax : expm1f(ax);
    ay = ay > 0.f ? ay : expm1f(ay);
    az = az > 0.f ? az : expm1f(az);
    aw = aw > 0.f ? aw : expm1f(aw);
    __half2 h01 = __floats2half2_rn(ax, ay);
    __half2 h23 = __floats2half2_rn(az, aw);
    __half2* o2 = (__half2*)(out + (long)n * F + f4 * 4);
    o2[0] = h01; o2[1] = h23;
}

// ---------------- pair readout: fp16 in/out ----------------
__global__ void k_pair(const __half* __restrict__ h,
                       const int* __restrict__ i1, const int* __restrict__ i2,
                       __half* __restrict__ xc)
{
    int p = blockIdx.x;
    int f = threadIdx.x;
    float v = (f < 128) ? __half2float(h[(long)i1[p] * 128 + f])
                        : __half2float(h[(long)i2[p] * 128 + (f - 128)]);
    __shared__ float red[256];
    red[f] = v * v;
    __syncthreads();
    for (int off = 128; off > 0; off >>= 1) {
        if (f < off) red[f] += red[f + off];
        __syncthreads();
    }
    float norm = fmaxf(sqrtf(red[0]), 1e-12f);
    xc[(long)p * 256 + f] = __float2half_rn(v / norm);
}

__global__ void k_out(const float* __restrict__ x, const float* __restrict__ W,
                      const float* __restrict__ b, float* __restrict__ out)
{
    int idx = blockIdx.x * blockDim.x + threadIdx.x;
    if (idx >= NB * 2) return;
    int p = idx >> 1, c = idx & 1;
    float acc = b[c];
#pragma unroll
    for (int k = 0; k < 64; k++) acc += x[p * 64 + k] * W[k * 2 + c];
    out[idx] = acc;
}

// ---------------- launch ----------------
extern "C" void kernel_launch(void* const* d_in, const int* in_sizes, int n_in,
                              void* d_out, int out_size)
{
    const float* cid   = (const float*)d_in[0];
    const int*   edges = (const int*)  d_in[1];
    const int*   i1    = (const int*)  d_in[2];
    const int*   i2    = (const int*)  d_in[3];
    const float* thr   = (const float*)d_in[4];
    const float* bb2W  = (const float*)d_in[5];  const float* bb2b = (const float*)d_in[6];
    const float* bb3W  = (const float*)d_in[7];  const float* bb3b = (const float*)d_in[8];
    const float* g1W   = (const float*)d_in[9];  const float* g1b  = (const float*)d_in[10];
    const float* g2W   = (const float*)d_in[11]; const float* g2b  = (const float*)d_in[12];
    const float* g3W   = (const float*)d_in[13]; const float* g3b  = (const float*)d_in[14];
    const float* g4W   = (const float*)d_in[15]; const float* g4b  = (const float*)d_in[16];
    const float* g5W   = (const float*)d_in[17]; const float* g5b  = (const float*)d_in[18];
    const float* f1W   = (const float*)d_in[19]; const float* f1b  = (const float*)d_in[20];
    const float* f2W   = (const float*)d_in[21]; const float* f2b  = (const float*)d_in[22];
    const float* f3W   = (const float*)d_in[23]; const float* f3b  = (const float*)d_in[24];
    const float* oW    = (const float*)d_in[25]; const float* ob   = (const float*)d_in[26];

    void *pcid, *px1, *px, *ph, *phw, *ppc, *pf1, *pf2, *pf3, *pwt;
    cudaGetSymbolAddress(&pcid, g_cid);
    cudaGetSymbolAddress(&px1,  g_x1);
    cudaGetSymbolAddress(&px,   g_x);
    cudaGetSymbolAddress(&ph,   g_h);
    cudaGetSymbolAddress(&phw,  g_hw);
    cudaGetSymbolAddress(&ppc,  g_pc);
    cudaGetSymbolAddress(&pf1,  g_f1);
    cudaGetSymbolAddress(&pf2,  g_f2);
    cudaGetSymbolAddress(&pf3,  g_f3);
    cudaGetSymbolAddress(&pwt,  g_wt);
    __half* cidp = (__half*)pcid;
    __half* x1   = (__half*)px1;
    __half* x    = (__half*)px;
    __half* h    = (__half*)ph;
    float*  hw   = (float*)phw;
    __half* pc   = (__half*)ppc;
    __half* f1o  = (__half*)pf1;
    float*  f2o  = (float*)pf2;
    float*  f3o  = (float*)pf3;
    __half* wt   = (__half*)pwt;

    // allow 60KB dynamic smem on all used GEMM instantiations
    cudaFuncSetAttribute(k_hgemm<2,1>, cudaFuncAttributeMaxDynamicSharedMemorySize, HG_SMEM);
    cudaFuncSetAttribute(k_hgemm<1,1>, cudaFuncAttributeMaxDynamicSharedMemorySize, HG_SMEM);
    cudaFuncSetAttribute(k_hgemm<0,0>, cudaFuncAttributeMaxDynamicSharedMemorySize, HG_SMEM);
    cudaFuncSetAttribute(k_hgemm<1,0>, cudaFuncAttributeMaxDynamicSharedMemorySize, HG_SMEM);

    int MY = NNP / 128;  // 235
    dim3 tb(32, 8);

    // --- BasicBlock first (profiling target: launch idx 3 = BB2 GEMM) ---
    k_pad_cid<<<(NNP * 896 + 255) / 256, 256>>>(cid);                       // 0
    k_zero_wt<<<(WT_ZERO + 255) / 256, 256>>>();                            // 1
    k_transpose2<<<dim3(28, 28), tb>>>(bb2W, wt + OFF_BB2, 881, 881, 896);  // 2
    k_hgemm<2,1><<<dim3(7, MY), 256, HG_SMEM>>>(cidp, wt + OFF_BB2, bb2b, thr, x1,
                                                NN, 881, 896, 896, 896, 896, 896);  // 3
    k_transpose2<<<dim3(8, 28),  tb>>>(bb3W, wt + OFF_BB3, 881, 256, 896);  // 4
    k_hgemm<1,1><<<dim3(2, MY), 256, HG_SMEM>>>(x1, wt + OFF_BB3, bb3b, nullptr, x,
                                                NN, 256, 896, 896, 896, 256, 256);  // 5

    // --- graph preprocessing (needed before first gather) ---
    k_zero_deg<<<(NN + 255) / 256, 256>>>();
    k_count<<<(NE + 255) / 256, 256>>>(edges);
    k_dinv<<<(NN + 255) / 256, 256>>>();
    k_scanA<<<NSB, 256>>>();
    k_scanB<<<1, 128>>>();
    k_scanC<<<NSB, 256>>>();
    k_fill<<<(NE + 255) / 256, 256>>>(edges);

    // --- remaining weight transposes ---
    k_transpose2<<<dim3(8, 8),   tb>>>(g1W,  wt + OFF_G1,  256, 256, 256);
    k_transpose2<<<dim3(8, 8),   tb>>>(g2W,  wt + OFF_G2,  256, 256, 256);
    k_transpose2<<<dim3(8, 8),   tb>>>(g3W,  wt + OFF_G3,  256, 256, 256);
    k_transpose2<<<dim3(4, 8),   tb>>>(g4W,  wt + OFF_G4,  256, 128, 256);
    k_transpose2<<<dim3(4, 4),   tb>>>(g5W,  wt + OFF_G5,  128, 128, 128);
    k_transpose2<<<dim3(32, 8),  tb>>>(f1W,  wt + OFF_F1,  256, 1024, 256);
    k_transpose2<<<dim3(8, 32),  tb>>>(f2W,  wt + OFF_F2,  1024, 256, 1024);

    // --- GCN layers (GEMM -> fp32 hw -> gather -> fp16) ---
    dim3 gat256(64, 4), gat128(32, 4);
    int  ngb = (NN + 3) / 4;
    k_hgemm<0,0><<<dim3(2, MY), 256, HG_SMEM>>>(x, wt + OFF_G1, nullptr, nullptr, hw,
                                                NN, 256, 256, 256, 256, 256, 256);
    k_gather<<<ngb, gat256>>>(hw, g1b, h, 256);
    k_hgemm<0,0><<<dim3(2, MY), 256, HG_SMEM>>>(h, wt + OFF_G2, nullptr, nullptr, hw,
                                                NN, 256, 256, 256, 256, 256, 256);
    k_gather<<<ngb, gat256>>>(hw, g2b, x, 256);
    k_hgemm<0,0><<<dim3(2, MY), 256, HG_SMEM>>>(x, wt + OFF_G3, nullptr, nullptr, hw,
                                                NN, 256, 256, 256, 256, 256, 256);
    k_gather<<<ngb, gat256>>>(hw, g3b, h, 256);
    k_hgemm<0,0><<<dim3(1, MY), 256, HG_SMEM>>>(h, wt + OFF_G4, nullptr, nullptr, hw,
                                                NN, 128, 256, 256, 256, 128, 128);
    k_gather<<<ngb, gat128>>>(hw, g4b, x, 128);
    k_hgemm<0,0><<<dim3(1, MY), 256, HG_SMEM>>>(x, wt + OFF_G5, nullptr, nullptr, hw,
                                                NN, 128, 128, 128, 128, 128, 128);
    k_gather<<<ngb, gat128>>>(hw, g5b, h, 128);

    // --- pair readout ---
    k_pair<<<NB, 256>>>(h, i1, i2, pc);
    k_hgemm<1,1><<<dim3(8, 32), 256, HG_SMEM>>>(pc,  wt + OFF_F1, f1b, nullptr, f1o,
                                                NB, 1024, 256, 256, 256, 1024, 1024);
    k_hgemm<1,0><<<dim3(2, 32), 256, HG_SMEM>>>(f1o, wt + OFF_F2, f2b, nullptr, f2o,
                                                NB, 256, 1024, 1024, 1024, 256, 256);
    k_sgemm<1><<<dim3(1, 32), 256>>>(f2o, f3W, f3b, nullptr, f3o, NB, 64, 256);
    k_out<<<(NB * 2 + 255) / 256, 256>>>(f3o, oW, ob, (float*)d_out);
}

// round 11
// speedup vs baseline: 1.0495x; 1.0303x over previous
#include <cuda_runtime.h>
#include <cuda_fp16.h>
#include <math.h>
#include <stdint.h>

#define NN 30000
#define NNP 30080   // padded to multiple of 128
#define NE 480000
#define NB 4096
#define NSB 118

// ---------------- device scratch ----------------
__device__ __align__(16) __half g_cid[NNP * 896];
__device__ __align__(16) __half g_x1[NNP * 896];
__device__ __align__(16) __half g_x [NNP * 256];
__device__ __align__(16) __half g_h [NNP * 256];
__device__ float g_hw[NNP * 256];          // GEMM out / gather in (fp32)
__device__ __align__(16) __half g_pc[NB * 256];    // pair out
__device__ __align__(16) __half g_f1[NB * 1024];   // f1 out
__device__ float g_f2[NB * 256];           // f2 out (feeds fp32 sgemm)
__device__ float g_f3[NB * 64];            // f3 out
__device__ float g_dinv[NN];
__device__ int   g_deg[NN];
__device__ int   g_cnt[NN];
__device__ int   g_rowptr[NN + 1];
__device__ int   g_col[NE];
__device__ float g_wgt[NE];
__device__ int   g_bsum[128];
__device__ int   g_boff[128];

// transposed fp16 weights (element offsets)
#define OFF_BB2 0                       // 896 x 896
#define OFF_BB3 (OFF_BB2 + 896*896)     // 256 x 896
#define OFF_G1  (OFF_BB3 + 256*896)     // 256 x 256
#define OFF_G2  (OFF_G1  + 256*256)
#define OFF_G3  (OFF_G2  + 256*256)
#define OFF_G4  (OFF_G3  + 256*256)    // 128 x 256
#define OFF_G5  (OFF_G4  + 128*256)    // 128 x 128
#define OFF_F1  (OFF_G5  + 128*128)    // 1024 x 256
#define OFF_F2  (OFF_F1  + 1024*256)   // 256 x 1024
#define WT_TOT  (OFF_F2  + 256*1024)
#define WT_ZERO (OFF_G1)               // zero-init BB2t + BB3t pad regions
__device__ __align__(16) __half g_wt[WT_TOT];

// ---------------- helpers ----------------
__device__ __forceinline__ uint32_t smem_u32(const void* p) {
    uint32_t a;
    asm("{ .reg .u64 t; cvta.to.shared.u64 t, %1; cvt.u32.u64 %0, t; }" : "=r"(a) : "l"(p));
    return a;
}
__device__ __forceinline__ void ldsm4(uint32_t& r0, uint32_t& r1, uint32_t& r2, uint32_t& r3,
                                      uint32_t addr) {
    asm volatile("ldmatrix.sync.aligned.m8n8.x4.shared.b16 {%0,%1,%2,%3}, [%4];"
                 : "=r"(r0), "=r"(r1), "=r"(r2), "=r"(r3) : "r"(addr));
}
#define CP16(d, s) asm volatile("cp.async.cg.shared.global [%0], [%1], 16;" :: "r"(d), "l"(s) : "memory")
#define CPCOMMIT() asm volatile("cp.async.commit_group;" ::: "memory")
template<int W> __device__ __forceinline__ void cp_wait() {
    asm volatile("cp.async.wait_group %0;" :: "n"(W) : "memory");
}

// ---------------- graph preprocessing ----------------
__global__ void k_zero_deg() {
    int i = blockIdx.x * blockDim.x + threadIdx.x;
    if (i < NN) { g_deg[i] = 0; g_cnt[i] = 0; }
}
__global__ void k_count(const int* __restrict__ edges) {
    int e = blockIdx.x * blockDim.x + threadIdx.x;
    if (e < NE) atomicAdd(&g_deg[edges[NE + e]], 1);
}
__global__ void k_dinv() {
    int i = blockIdx.x * blockDim.x + threadIdx.x;
    if (i < NN) g_dinv[i] = rsqrtf((float)(g_deg[i] + 1));
}
__global__ void k_scanA() {
    __shared__ int sh[256];
    int tid = threadIdx.x;
    int i = blockIdx.x * 256 + tid;
    int v = (i < NN) ? g_deg[i] : 0;
    sh[tid] = v;
    __syncthreads();
#pragma unroll
    for (int off = 1; off < 256; off <<= 1) {
        int t = (tid >= off) ? sh[tid - off] : 0;
        __syncthreads();
        sh[tid] += t;
        __syncthreads();
    }
    if (i < NN) g_rowptr[i] = sh[tid] - v;
    if (tid == 255) g_bsum[blockIdx.x] = sh[255];
}
__global__ void k_scanB() {
    __shared__ int sh[128];
    int tid = threadIdx.x;
    int v = (tid < NSB) ? g_bsum[tid] : 0;
    sh[tid] = v;
    __syncthreads();
#pragma unroll
    for (int off = 1; off < 128; off <<= 1) {
        int t = (tid >= off) ? sh[tid - off] : 0;
        __syncthreads();
        sh[tid] += t;
        __syncthreads();
    }
    if (tid < NSB) g_boff[tid] = sh[tid] - v;
    if (tid == 127) g_rowptr[NN] = sh[127];
}
__global__ void k_scanC() {
    int i = blockIdx.x * 256 + threadIdx.x;
    if (i < NN) g_rowptr[i] += g_boff[blockIdx.x];
}
__global__ void k_fill(const int* __restrict__ edges) {
    int e = blockIdx.x * blockDim.x + threadIdx.x;
    if (e < NE) {
        int s = edges[e];
        int d = edges[NE + e];
        int pos = g_rowptr[d] + atomicAdd(&g_cnt[d], 1);
        g_col[pos] = s;
        g_wgt[pos] = g_dinv[s] * g_dinv[d];
    }
}

// ---------------- producers: pad + fp16-convert ----------------
__global__ void k_pad_cid(const float* __restrict__ cid) {
    int idx = blockIdx.x * 256 + threadIdx.x;
    if (idx >= NNP * 896) return;
    int row = idx / 896, col = idx - row * 896;
    g_cid[idx] = __float2half_rn((row < NN && col < 881) ? cid[(long)row * 881 + col] : 0.f);
}
__global__ void k_zero_wt() {
    int i = blockIdx.x * 256 + threadIdx.x;
    if (i < WT_ZERO) g_wt[i] = __float2half_rn(0.f);
}
// dst[c*dld + r] = fp16(src[r*C + c])
__global__ void k_transpose2(const float* __restrict__ src, __half* __restrict__ dst,
                             int R, int C, int dld) {
    __shared__ float t[32][33];
    int c0 = blockIdx.x * 32, r0 = blockIdx.y * 32;
    int x = threadIdx.x, y = threadIdx.y;  // 32 x 8
#pragma unroll
    for (int i = 0; i < 4; i++) {
        int r = r0 + y + i * 8;
        if (r < R && c0 + x < C) t[y + i * 8][x] = src[(long)r * C + c0 + x];
    }
    __syncthreads();
#pragma unroll
    for (int i = 0; i < 4; i++) {
        int c = c0 + y + i * 8;
        if (c < C && r0 + x < R) dst[(long)c * dld + r0 + x] = __float2half_rn(t[x][y + i * 8]);
    }
}

// ---------------- fp16 mma.sync GEMM, cp.async 3-stage, ldmatrix frags -----
// C[M,N] = A[M,Kpad] @ Bt[N,Kpad]^T, fp16 operands, fp32 accum.
// EPI: 0 none, 1 relu+bias, 2 relu+softthr+bias. OUTH: 1 -> half out, 0 -> float.
// Requires Kpad multiple of 32 and Kpad >= 64 (nch >= 2).
#define SMSH 40   // smem row stride in halfs (32 data + 8 pad)
#define HG_STAGE (128 * SMSH)              // halfs per operand per stage
#define HG_SMEM  (3 * HG_STAGE * 2 * 2)    // bytes: 3 stages x (A+B)
template <int EPI, int OUTH>
__global__ __launch_bounds__(256, 2) void k_hgemm(
    const __half* __restrict__ A, const __half* __restrict__ Bt,
    const float* __restrict__ bias, const float* __restrict__ thr_p,
    void* __restrict__ Cv, int M, int N, int Kpad, int lda, int ldb, int ldc, int fillw)
{
    extern __shared__ __align__(16) __half sm[];
    __half* smA = sm;                      // 3 x HG_STAGE
    __half* smB = sm + 3 * HG_STAGE;       // 3 x HG_STAGE
    int tid = threadIdx.x, wid = tid >> 5, lane = tid & 31;
    int row0 = blockIdx.y * 128, col0 = blockIdx.x * 128;
    int wr = wid >> 2, wc = wid & 3;       // warp grid 2 x 4, warp tile 64 x 32
    int q = lane >> 2, t4 = lane & 3;

    int r0 = tid >> 2, off = (tid & 3) * 8;   // cp.async coords (halfs)
    int r1 = r0 + 64;
    const __half* pA0 = A + (long)(row0 + r0) * lda + off;
    const __half* pA1 = A + (long)(row0 + r1) * lda + off;
    const __half* pB0 = Bt + (long)(col0 + r0) * ldb + off;
    const __half* pB1 = Bt + (long)(col0 + r1) * ldb + off;
    uint32_t aA = smem_u32(smA), aB = smem_u32(smB);
    uint32_t dA0 = aA + (r0 * SMSH + off) * 2;
    uint32_t dA1 = aA + (r1 * SMSH + off) * 2;
    uint32_t dB0 = aB + (r0 * SMSH + off) * 2;
    uint32_t dB1 = aB + (r1 * SMSH + off) * 2;
    const uint32_t STo = HG_STAGE * 2;     // per-stage bytes

    // ldmatrix lane-relative offsets (bytes)
    int la = lane & 7, lg = lane >> 3;     // lg in 0..3
    // A: matrices (rows0-7,k0-7),(rows8-15,k0-7),(rows0-7,k8-15),(rows8-15,k8-15)
    uint32_t offLA = (uint32_t)(((la + (lg & 1) * 8) * SMSH + (lg >> 1) * 8) * 2);
    // B: matrices (n0-7,k0-7),(n0-7,k8-15),(n8-15,k0-7),(n8-15,k8-15)
    uint32_t offLB = (uint32_t)(((la + (lg >> 1) * 8) * SMSH + (lg & 1) * 8) * 2);
    uint32_t baseLA = aA + offLA + (uint32_t)(wr * 64 * SMSH * 2);
    uint32_t baseLB = aB + offLB + (uint32_t)(wc * 32 * SMSH * 2);

    float acc[16][4];
#pragma unroll
    for (int i = 0; i < 16; i++)
#pragma unroll
        for (int j = 0; j < 4; j++) acc[i][j] = 0.f;

    int nch = Kpad >> 5;    // 32-K chunks (nch >= 2 by contract)
    // prologue: stages 0 and 1
    CP16(dA0, pA0); CP16(dA1, pA1); CP16(dB0, pB0); CP16(dB1, pB1);
    CPCOMMIT();
    {
        int k0 = 32;
        CP16(dA0 + STo, pA0 + k0); CP16(dA1 + STo, pA1 + k0);
        CP16(dB0 + STo, pB0 + k0); CP16(dB1 + STo, pB1 + k0);
        CPCOMMIT();
    }

    for (int ch = 0; ch < nch; ch++) {
        if (ch + 2 < nch) {
            int k0 = (ch + 2) << 5;
            uint32_t o = ((ch + 2) % 3) * STo;
            CP16(dA0 + o, pA0 + k0); CP16(dA1 + o, pA1 + k0);
            CP16(dB0 + o, pB0 + k0); CP16(dB1 + o, pB1 + k0);
            CPCOMMIT();
            cp_wait<2>();
        } else if (ch + 1 < nch) {
            cp_wait<1>();
        } else {
            cp_wait<0>();
        }
        __syncthreads();
        uint32_t stA = baseLA + (ch % 3) * STo;
        uint32_t stB = baseLB + (ch % 3) * STo;
#pragma unroll
        for (int s = 0; s < 2; s++) {
            uint32_t af[4][4], bf[4][2];
#pragma unroll
            for (int tm = 0; tm < 4; tm++)
                ldsm4(af[tm][0], af[tm][1], af[tm][2], af[tm][3],
                      stA + (uint32_t)(tm * 16 * SMSH * 2) + (uint32_t)(s * 32));
#pragma unroll
            for (int tn = 0; tn < 4; tn += 2)
                ldsm4(bf[tn][0], bf[tn][1], bf[tn + 1][0], bf[tn + 1][1],
                      stB + (uint32_t)(tn * 8 * SMSH * 2) + (uint32_t)(s * 32));
#pragma unroll
            for (int tm = 0; tm < 4; tm++)
#pragma unroll
                for (int tn = 0; tn < 4; tn++) {
                    float* c = acc[tm * 4 + tn];
                    asm volatile(
                        "mma.sync.aligned.m16n8k16.row.col.f32.f16.f16.f32 "
                        "{%0,%1,%2,%3}, {%4,%5,%6,%7}, {%8,%9}, {%0,%1,%2,%3};"
                        : "+f"(c[0]), "+f"(c[1]), "+f"(c[2]), "+f"(c[3])
                        : "r"(af[tm][0]), "r"(af[tm][1]), "r"(af[tm][2]), "r"(af[tm][3]),
                          "r"(bf[tn][0]), "r"(bf[tn][1]));
                }
        }
        __syncthreads();
    }

    // epilogue
    float thr = (EPI == 2) ? thr_p[0] : 0.f;
#pragma unroll
    for (int tm = 0; tm < 4; tm++) {
#pragma unroll
        for (int half_ = 0; half_ < 2; half_++) {
            int gr = row0 + wr * 64 + tm * 16 + q + half_ * 8;
            if (gr >= M) continue;
#pragma unroll
            for (int tn = 0; tn < 4; tn++) {
#pragma unroll
                for (int cc = 0; cc < 2; cc++) {
                    int gc = col0 + wc * 32 + tn * 8 + 2 * t4 + cc;
                    if (gc >= fillw) continue;
                    float v = 0.f;
                    if (gc < N) {
                        v = acc[tm * 4 + tn][half_ * 2 + cc];
                        if (EPI != 0) v += bias[gc];
                        if (EPI == 1) v = fmaxf(v, 0.f);
                        if (EPI == 2) { v = fmaxf(v, 0.f); v = fmaxf(v - thr, 0.f); }
                    }
                    if (OUTH) ((__half*)Cv)[(long)gr * ldc + gc] = __float2half_rn(v);
                    else      ((float*)Cv)[(long)gr * ldc + gc] = v;
                }
            }
        }
    }
}

// ---------------- fp32 SGEMM (f3 tail layer) ----------------
#define BM 128
#define BN 128
#define BK 16
#define AP 132
template <int EPI>
__global__ __launch_bounds__(256, 2) void k_sgemm(
    const float* __restrict__ A, const float* __restrict__ B,
    const float* __restrict__ bias, const float* __restrict__ thr_p,
    float* __restrict__ C, int M, int N, int K)
{
    __shared__ float As[2][BK][AP];
    __shared__ float Bs[2][BK][BN];
    int tid = threadIdx.x;
    int row0 = blockIdx.y * BM, col0 = blockIdx.x * BN;
    int tx = tid & 15, ty = tid >> 4;
    int ar[8], ac[8], br[8], bc[8];
#pragma unroll
    for (int i = 0; i < 8; i++) {
        int idx = i * 256 + tid;
        ar[i] = idx >> 4;  ac[i] = idx & 15;
        br[i] = idx >> 7;  bc[i] = idx & 127;
    }
    float acc[8][8];
#pragma unroll
    for (int i = 0; i < 8; i++)
#pragma unroll
        for (int j = 0; j < 8; j++) acc[i][j] = 0.f;
    float ldA[8], ldB[8];
    int nt = (K + BK - 1) / BK;
#pragma unroll
    for (int i = 0; i < 8; i++) {
        int gr = row0 + ar[i], gc = ac[i];
        ldA[i] = (gr < M && gc < K) ? A[(long)gr * K + gc] : 0.f;
        int hr = br[i], hc = col0 + bc[i];
        ldB[i] = (hr < K && hc < N) ? B[(long)hr * N + hc] : 0.f;
    }
#pragma unroll
    for (int i = 0; i < 8; i++) { As[0][ac[i]][ar[i]] = ldA[i]; Bs[0][br[i]][bc[i]] = ldB[i]; }
    __syncthreads();
    int cur = 0;
    for (int t = 0; t < nt; t++) {
        int kn = (t + 1) * BK;
        if (t + 1 < nt) {
#pragma unroll
            for (int i = 0; i < 8; i++) {
                int gr = row0 + ar[i], gc = kn + ac[i];
                ldA[i] = (gr < M && gc < K) ? A[(long)gr * K + gc] : 0.f;
                int hr = kn + br[i], hc = col0 + bc[i];
                ldB[i] = (hr < K && hc < N) ? B[(long)hr * N + hc] : 0.f;
            }
        }
#pragma unroll
        for (int kk = 0; kk < BK; kk++) {
            float4 a0 = *(const float4*)&As[cur][kk][ty * 8];
            float4 a1 = *(const float4*)&As[cur][kk][ty * 8 + 4];
            float4 b0 = *(const float4*)&Bs[cur][kk][tx * 8];
            float4 b1 = *(const float4*)&Bs[cur][kk][tx * 8 + 4];
            float ra[8] = {a0.x, a0.y, a0.z, a0.w, a1.x, a1.y, a1.z, a1.w};
            float rb[8] = {b0.x, b0.y, b0.z, b0.w, b1.x, b1.y, b1.z, b1.w};
#pragma unroll
            for (int i = 0; i < 8; i++)
#pragma unroll
                for (int j = 0; j < 8; j++) acc[i][j] = fmaf(ra[i], rb[j], acc[i][j]);
        }
        if (t + 1 < nt) {
            int nxt = cur ^ 1;
#pragma unroll
            for (int i = 0; i < 8; i++) { As[nxt][ac[i]][ar[i]] = ldA[i]; Bs[nxt][br[i]][bc[i]] = ldB[i]; }
            __syncthreads();
            cur = nxt;
        }
    }
    float thr = (EPI == 2) ? thr_p[0] : 0.f;
#pragma unroll
    for (int i = 0; i < 8; i++) {
        int gr = row0 + ty * 8 + i;
        if (gr >= M) continue;
#pragma unroll
        for (int j = 0; j < 8; j++) {
            int gc = col0 + tx * 8 + j;
            if (gc >= N) continue;
            float v = acc[i][j] + (bias ? bias[gc] : 0.f);
            if (EPI == 1) v = fmaxf(v, 0.f);
            if (EPI == 2) { v = fmaxf(v, 0.f); v = fmaxf(v - thr, 0.f); }
            C[(long)gr * N + gc] = v;
        }
    }
}

// ---------------- GCN gather: fp32 in (hw), fp16 out (next GEMM A) ---------
__global__ void k_gather(const float* __restrict__ hw, const float* __restrict__ bias,
                         __half* __restrict__ out, int F)
{
    int n = blockIdx.x * 4 + threadIdx.y;
    if (n >= NN) return;
    int f4 = threadIdx.x;
    int Fq = F >> 2;
    const float4* __restrict__ hw4 = (const float4*)hw;
    float d = g_dinv[n];
    float c = d * d;
    float4 sv = hw4[(long)n * Fq + f4];
    float ax = sv.x * c, ay = sv.y * c, az = sv.z * c, aw = sv.w * c;
    int s = g_rowptr[n], e = g_rowptr[n + 1];
    int i = s;
    for (; i + 4 <= e; i += 4) {
        int   c0 = g_col[i],  c1 = g_col[i + 1], c2 = g_col[i + 2], c3 = g_col[i + 3];
        float w0 = g_wgt[i],  w1 = g_wgt[i + 1], w2 = g_wgt[i + 2], w3 = g_wgt[i + 3];
        float4 v0 = hw4[(long)c0 * Fq + f4];
        float4 v1 = hw4[(long)c1 * Fq + f4];
        float4 v2 = hw4[(long)c2 * Fq + f4];
        float4 v3 = hw4[(long)c3 * Fq + f4];
        ax += w0 * v0.x + w1 * v1.x + w2 * v2.x + w3 * v3.x;
        ay += w0 * v0.y + w1 * v1.y + w2 * v2.y + w3 * v3.y;
        az += w0 * v0.z + w1 * v1.z + w2 * v2.z + w3 * v3.z;
        aw += w0 * v0.w + w1 * v1.w + w2 * v2.w + w3 * v3.w;
    }
    for (; i < e; i++) {
        int c0 = g_col[i]; float w0 = g_wgt[i];
        float4 v0 = hw4[(long)c0 * Fq + f4];
        ax += w0 * v0.x; ay += w0 * v0.y; az += w0 * v0.z; aw += w0 * v0.w;
    }
    float4 b = ((const float4*)bias)[f4];
    ax += b.x; ay += b.y; az += b.z; aw += b.w;
    ax = ax > 0.f ? ax : expm1f(ax);
    ay = ay > 0.f ? ay : expm1f(ay);
    az = az > 0.f ? az : expm1f(az);
    aw = aw > 0.f ? aw : expm1f(aw);
    __half2 h01 = __floats2half2_rn(ax, ay);
    __half2 h23 = __floats2half2_rn(az, aw);
    __half2* o2 = (__half2*)(out + (long)n * F + f4 * 4);
    o2[0] = h01; o2[1] = h23;
}

// ---------------- pair readout: fp16 in/out ----------------
__global__ void k_pair(const __half* __restrict__ h,
                       const int* __restrict__ i1, const int* __restrict__ i2,
                       __half* __restrict__ xc)
{
    int p = blockIdx.x;
    int f = threadIdx.x;
    float v = (f < 128) ? __half2float(h[(long)i1[p] * 128 + f])
                        : __half2float(h[(long)i2[p] * 128 + (f - 128)]);
    __shared__ float red[256];
    red[f] = v * v;
    __syncthreads();
    for (int off = 128; off > 0; off >>= 1) {
        if (f < off) red[f] += red[f + off];
        __syncthreads();
    }
    float norm = fmaxf(sqrtf(red[0]), 1e-12f);
    xc[(long)p * 256 + f] = __float2half_rn(v / norm);
}

__global__ void k_out(const float* __restrict__ x, const float* __restrict__ W,
                      const float* __restrict__ b, float* __restrict__ out)
{
    int idx = blockIdx.x * blockDim.x + threadIdx.x;
    if (idx >= NB * 2) return;
    int p = idx >> 1, c = idx & 1;
    float acc = b[c];
#pragma unroll
    for (int k = 0; k < 64; k++) acc += x[p * 64 + k] * W[k * 2 + c];
    out[idx] = acc;
}

// ---------------- launch ----------------
extern "C" void kernel_launch(void* const* d_in, const int* in_sizes, int n_in,
                              void* d_out, int out_size)
{
    const float* cid   = (const float*)d_in[0];
    const int*   edges = (const int*)  d_in[1];
    const int*   i1    = (const int*)  d_in[2];
    const int*   i2    = (const int*)  d_in[3];
    const float* thr   = (const float*)d_in[4];
    const float* bb2W  = (const float*)d_in[5];  const float* bb2b = (const float*)d_in[6];
    const float* bb3W  = (const float*)d_in[7];  const float* bb3b = (const float*)d_in[8];
    const float* g1W   = (const float*)d_in[9];  const float* g1b  = (const float*)d_in[10];
    const float* g2W   = (const float*)d_in[11]; const float* g2b  = (const float*)d_in[12];
    const float* g3W   = (const float*)d_in[13]; const float* g3b  = (const float*)d_in[14];
    const float* g4W   = (const float*)d_in[15]; const float* g4b  = (const float*)d_in[16];
    const float* g5W   = (const float*)d_in[17]; const float* g5b  = (const float*)d_in[18];
    const float* f1W   = (const float*)d_in[19]; const float* f1b  = (const float*)d_in[20];
    const float* f2W   = (const float*)d_in[21]; const float* f2b  = (const float*)d_in[22];
    const float* f3W   = (const float*)d_in[23]; const float* f3b  = (const float*)d_in[24];
    const float* oW    = (const float*)d_in[25]; const float* ob   = (const float*)d_in[26];

    void *pcid, *px1, *px, *ph, *phw, *ppc, *pf1, *pf2, *pf3, *pwt;
    cudaGetSymbolAddress(&pcid, g_cid);
    cudaGetSymbolAddress(&px1,  g_x1);
    cudaGetSymbolAddress(&px,   g_x);
    cudaGetSymbolAddress(&ph,   g_h);
    cudaGetSymbolAddress(&phw,  g_hw);
    cudaGetSymbolAddress(&ppc,  g_pc);
    cudaGetSymbolAddress(&pf1,  g_f1);
    cudaGetSymbolAddress(&pf2,  g_f2);
    cudaGetSymbolAddress(&pf3,  g_f3);
    cudaGetSymbolAddress(&pwt,  g_wt);
    __half* cidp = (__half*)pcid;
    __half* x1   = (__half*)px1;
    __half* x    = (__half*)px;
    __half* h    = (__half*)ph;
    float*  hw   = (float*)phw;
    __half* pc   = (__half*)ppc;
    __half* f1o  = (__half*)pf1;
    float*  f2o  = (float*)pf2;
    float*  f3o  = (float*)pf3;
    __half* wt   = (__half*)pwt;

    // allow 60KB dynamic smem on all used GEMM instantiations
    cudaFuncSetAttribute(k_hgemm<2,1>, cudaFuncAttributeMaxDynamicSharedMemorySize, HG_SMEM);
    cudaFuncSetAttribute(k_hgemm<1,1>, cudaFuncAttributeMaxDynamicSharedMemorySize, HG_SMEM);
    cudaFuncSetAttribute(k_hgemm<0,0>, cudaFuncAttributeMaxDynamicSharedMemorySize, HG_SMEM);
    cudaFuncSetAttribute(k_hgemm<1,0>, cudaFuncAttributeMaxDynamicSharedMemorySize, HG_SMEM);

    int MY = NNP / 128;  // 235
    dim3 tb(32, 8);

    // --- BasicBlock first (profiling target: launch idx 3 = BB2 GEMM) ---
    k_pad_cid<<<(NNP * 896 + 255) / 256, 256>>>(cid);                       // 0
    k_zero_wt<<<(WT_ZERO + 255) / 256, 256>>>();                            // 1
    k_transpose2<<<dim3(28, 28), tb>>>(bb2W, wt + OFF_BB2, 881, 881, 896);  // 2
    k_hgemm<2,1><<<dim3(7, MY), 256, HG_SMEM>>>(cidp, wt + OFF_BB2, bb2b, thr, x1,
                                                NN, 881, 896, 896, 896, 896, 896);  // 3
    k_transpose2<<<dim3(8, 28),  tb>>>(bb3W, wt + OFF_BB3, 881, 256, 896);  // 4
    k_hgemm<1,1><<<dim3(2, MY), 256, HG_SMEM>>>(x1, wt + OFF_BB3, bb3b, nullptr, x,
                                                NN, 256, 896, 896, 896, 256, 256);  // 5

    // --- graph preprocessing (needed before first gather) ---
    k_zero_deg<<<(NN + 255) / 256, 256>>>();
    k_count<<<(NE + 255) / 256, 256>>>(edges);
    k_dinv<<<(NN + 255) / 256, 256>>>();
    k_scanA<<<NSB, 256>>>();
    k_scanB<<<1, 128>>>();
    k_scanC<<<NSB, 256>>>();
    k_fill<<<(NE + 255) / 256, 256>>>(edges);

    // --- remaining weight transposes ---
    k_transpose2<<<dim3(8, 8),   tb>>>(g1W,  wt + OFF_G1,  256, 256, 256);
    k_transpose2<<<dim3(8, 8),   tb>>>(g2W,  wt + OFF_G2,  256, 256, 256);
    k_transpose2<<<dim3(8, 8),   tb>>>(g3W,  wt + OFF_G3,  256, 256, 256);
    k_transpose2<<<dim3(4, 8),   tb>>>(g4W,  wt + OFF_G4,  256, 128, 256);
    k_transpose2<<<dim3(4, 4),   tb>>>(g5W,  wt + OFF_G5,  128, 128, 128);
    k_transpose2<<<dim3(32, 8),  tb>>>(f1W,  wt + OFF_F1,  256, 1024, 256);
    k_transpose2<<<dim3(8, 32),  tb>>>(f2W,  wt + OFF_F2,  1024, 256, 1024);

    // --- GCN layers (GEMM -> fp32 hw -> gather -> fp16) ---
    dim3 gat256(64, 4), gat128(32, 4);
    int  ngb = (NN + 3) / 4;
    k_hgemm<0,0><<<dim3(2, MY), 256, HG_SMEM>>>(x, wt + OFF_G1, nullptr, nullptr, hw,
                                                NN, 256, 256, 256, 256, 256, 256);
    k_gather<<<ngb, gat256>>>(hw, g1b, h, 256);
    k_hgemm<0,0><<<dim3(2, MY), 256, HG_SMEM>>>(h, wt + OFF_G2, nullptr, nullptr, hw,
                                                NN, 256, 256, 256, 256, 256, 256);
    k_gather<<<ngb, gat256>>>(hw, g2b, x, 256);
    k_hgemm<0,0><<<dim3(2, MY), 256, HG_SMEM>>>(x, wt + OFF_G3, nullptr, nullptr, hw,
                                                NN, 256, 256, 256, 256, 256, 256);
    k_gather<<<ngb, gat256>>>(hw, g3b, h, 256);
    k_hgemm<0,0><<<dim3(1, MY), 256, HG_SMEM>>>(h, wt + OFF_G4, nullptr, nullptr, hw,
                                                NN, 128, 256, 256, 256, 128, 128);
    k_gather<<<ngb, gat128>>>(hw, g4b, x, 128);
    k_hgemm<0,0><<<dim3(1, MY), 256, HG_SMEM>>>(x, wt + OFF_G5, nullptr, nullptr, hw,
                                                NN, 128, 128, 128, 128, 128, 128);
    k_gather<<<ngb, gat128>>>(hw, g5b, h, 128);

    // --- pair readout ---
    k_pair<<<NB, 256>>>(h, i1, i2, pc);
    k_hgemm<1,1><<<dim3(8, 32), 256, HG_SMEM>>>(pc,  wt + OFF_F1, f1b, nullptr, f1o,
                                                NB, 1024, 256, 256, 256, 1024, 1024);
    k_hgemm<1,0><<<dim3(2, 32), 256, HG_SMEM>>>(f1o, wt + OFF_F2, f2b, nullptr, f2o,
                                                NB, 256, 1024, 1024, 1024, 256, 256);
    k_sgemm<1><<<dim3(1, 32), 256>>>(f2o, f3W, f3b, nullptr, f3o, NB, 64, 256);
    k_out<<<(NB * 2 + 255) / 256, 256>>>(f3o, oW, ob, (float*)d_out);
}

// round 13
// speedup vs baseline: 1.0839x; 1.0328x over previous
#include <cuda_runtime.h>
#include <cuda_fp16.h>
#include <math.h>
#include <stdint.h>

#define NN 30000
#define NNP 30080   // padded to multiple of 128
#define NE 480000
#define NB 4096
#define NSB 118

// ---------------- device scratch ----------------
__device__ __align__(16) __half g_cid[NNP * 896];
__device__ __align__(16) __half g_x1[NNP * 896];
__device__ __align__(16) __half g_x [NNP * 256];
__device__ __align__(16) __half g_h [NNP * 256];
__device__ float g_hw[NNP * 256];          // GEMM out / gather in (fp32)
__device__ __align__(16) __half g_pc[NB * 256];    // pair out
__device__ __align__(16) __half g_f1[NB * 1024];   // f1 out
__device__ float g_f2[NB * 256];           // f2 out (feeds fp32 sgemm)
__device__ float g_f3[NB * 64];            // f3 out
__device__ float g_dinv[NN];
__device__ int   g_deg[NN];
__device__ int   g_cnt[NN];
__device__ int   g_rowptr[NN + 1];
__device__ int   g_col[NE];
__device__ float g_wgt[NE];
__device__ int   g_bsum[128];
__device__ int   g_boff[128];

// transposed fp16 weights (element offsets)
#define OFF_BB2 0                       // 896 x 896
#define OFF_BB3 (OFF_BB2 + 896*896)     // 256 x 896
#define OFF_G1  (OFF_BB3 + 256*896)     // 256 x 256
#define OFF_G2  (OFF_G1  + 256*256)
#define OFF_G3  (OFF_G2  + 256*256)
#define OFF_G4  (OFF_G3  + 256*256)    // 128 x 256
#define OFF_G5  (OFF_G4  + 128*256)    // 128 x 128
#define OFF_F1  (OFF_G5  + 128*128)    // 1024 x 256
#define OFF_F2  (OFF_F1  + 1024*256)   // 256 x 1024
#define WT_TOT  (OFF_F2  + 256*1024)
__device__ __align__(16) __half g_wt[WT_TOT];

// ---------------- helpers ----------------
__device__ __forceinline__ uint32_t smem_u32(const void* p) {
    uint32_t a;
    asm("{ .reg .u64 t; cvta.to.shared.u64 t, %1; cvt.u32.u64 %0, t; }" : "=r"(a) : "l"(p));
    return a;
}
__device__ __forceinline__ void ldsm4(uint32_t& r0, uint32_t& r1, uint32_t& r2, uint32_t& r3,
                                      uint32_t addr) {
    asm volatile("ldmatrix.sync.aligned.m8n8.x4.shared.b16 {%0,%1,%2,%3}, [%4];"
                 : "=r"(r0), "=r"(r1), "=r"(r2), "=r"(r3) : "r"(addr));
}
#define CP16(d, s) asm volatile("cp.async.cg.shared.global [%0], [%1], 16;" :: "r"(d), "l"(s) : "memory")
#define CPCOMMIT() asm volatile("cp.async.commit_group;" ::: "memory")
template<int W> __device__ __forceinline__ void cp_wait() {
    asm volatile("cp.async.wait_group %0;" :: "n"(W) : "memory");
}

// ---------------- graph preprocessing ----------------
__global__ void k_zero_deg() {
    int i = blockIdx.x * blockDim.x + threadIdx.x;
    if (i < NN) { g_deg[i] = 0; g_cnt[i] = 0; }
}
__global__ void k_count(const int* __restrict__ edges) {
    int e = blockIdx.x * blockDim.x + threadIdx.x;
    if (e < NE) atomicAdd(&g_deg[edges[NE + e]], 1);
}
__global__ void k_dinv() {
    int i = blockIdx.x * blockDim.x + threadIdx.x;
    if (i < NN) g_dinv[i] = rsqrtf((float)(g_deg[i] + 1));
}
__global__ void k_scanA() {
    __shared__ int sh[256];
    int tid = threadIdx.x;
    int i = blockIdx.x * 256 + tid;
    int v = (i < NN) ? g_deg[i] : 0;
    sh[tid] = v;
    __syncthreads();
#pragma unroll
    for (int off = 1; off < 256; off <<= 1) {
        int t = (tid >= off) ? sh[tid - off] : 0;
        __syncthreads();
        sh[tid] += t;
        __syncthreads();
    }
    if (i < NN) g_rowptr[i] = sh[tid] - v;
    if (tid == 255) g_bsum[blockIdx.x] = sh[255];
}
__global__ void k_scanB() {
    __shared__ int sh[128];
    int tid = threadIdx.x;
    int v = (tid < NSB) ? g_bsum[tid] : 0;
    sh[tid] = v;
    __syncthreads();
#pragma unroll
    for (int off = 1; off < 128; off <<= 1) {
        int t = (tid >= off) ? sh[tid - off] : 0;
        __syncthreads();
        sh[tid] += t;
        __syncthreads();
    }
    if (tid < NSB) g_boff[tid] = sh[tid] - v;
    if (tid == 127) g_rowptr[NN] = sh[127];
}
__global__ void k_scanC() {
    int i = blockIdx.x * 256 + threadIdx.x;
    if (i < NN) g_rowptr[i] += g_boff[blockIdx.x];
}
__global__ void k_fill(const int* __restrict__ edges) {
    int e = blockIdx.x * blockDim.x + threadIdx.x;
    if (e < NE) {
        int s = edges[e];
        int d = edges[NE + e];
        int pos = g_rowptr[d] + atomicAdd(&g_cnt[d], 1);
        g_col[pos] = s;
        g_wgt[pos] = g_dinv[s] * g_dinv[d];
    }
}

// ---------------- producers: pad + fp16-convert ----------------
__global__ void k_pad_cid(const float* __restrict__ cid) {
    int idx = blockIdx.x * 256 + threadIdx.x;
    if (idx >= NNP * 896) return;
    int row = idx / 896, col = idx - row * 896;
    g_cid[idx] = __float2half_rn((row < NN && col < 881) ? cid[(long)row * 881 + col] : 0.f);
}
// dst[c*dld + r] = fp16(src[r*C + c]); writes full padded region [Cp rows x Rp cols], zeros outside
__global__ void k_transposeP(const float* __restrict__ src, __half* __restrict__ dst,
                             int R, int C, int dld, int Rp, int Cp) {
    __shared__ float t[32][33];
    int c0 = blockIdx.x * 32, r0 = blockIdx.y * 32;
    int x = threadIdx.x, y = threadIdx.y;  // 32 x 8
#pragma unroll
    for (int i = 0; i < 4; i++) {
        int r = r0 + y + i * 8;
        t[y + i * 8][x] = (r < R && c0 + x < C) ? src[(long)r * C + c0 + x] : 0.f;
    }
    __syncthreads();
#pragma unroll
    for (int i = 0; i < 4; i++) {
        int c = c0 + y + i * 8;
        if (c < Cp && r0 + x < Rp) dst[(long)c * dld + r0 + x] = __float2half_rn(t[x][y + i * 8]);
    }
}

// ---------------- fp16 mma.sync GEMM, cp.async 3-stage, ldmatrix frags -----
// C[M,N] = A[M,Kpad] @ Bt[N,Kpad]^T, fp16 operands, fp32 accum.
// EPI: 0 none, 1 relu+bias, 2 relu+softthr+bias. OUTH: 1 -> half out, 0 -> float.
// Requires Kpad multiple of 32 and Kpad >= 64 (nch >= 2).
#define SMSH 40   // smem row stride in halfs (32 data + 8 pad)
#define HG_STAGE (128 * SMSH)              // halfs per operand per stage
#define HG_SMEM  (3 * HG_STAGE * 2 * 2)    // bytes: 3 stages x (A+B)
template <int EPI, int OUTH>
__global__ __launch_bounds__(256, 2) void k_hgemm(
    const __half* __restrict__ A, const __half* __restrict__ Bt,
    const float* __restrict__ bias, const float* __restrict__ thr_p,
    void* __restrict__ Cv, int M, int N, int Kpad, int lda, int ldb, int ldc, int fillw)
{
    extern __shared__ __align__(16) __half sm[];
    __half* smA = sm;                      // 3 x HG_STAGE
    __half* smB = sm + 3 * HG_STAGE;       // 3 x HG_STAGE
    int tid = threadIdx.x, wid = tid >> 5, lane = tid & 31;
    int row0 = blockIdx.y * 128, col0 = blockIdx.x * 128;
    int wr = wid >> 2, wc = wid & 3;       // warp grid 2 x 4, warp tile 64 x 32
    int q = lane >> 2, t4 = lane & 3;

    int r0 = tid >> 2, off = (tid & 3) * 8;   // cp.async coords (halfs)
    int r1 = r0 + 64;
    const __half* pA0 = A + (long)(row0 + r0) * lda + off;
    const __half* pA1 = A + (long)(row0 + r1) * lda + off;
    const __half* pB0 = Bt + (long)(col0 + r0) * ldb + off;
    const __half* pB1 = Bt + (long)(col0 + r1) * ldb + off;
    uint32_t aA = smem_u32(smA), aB = smem_u32(smB);
    uint32_t dA0 = aA + (r0 * SMSH + off) * 2;
    uint32_t dA1 = aA + (r1 * SMSH + off) * 2;
    uint32_t dB0 = aB + (r0 * SMSH + off) * 2;
    uint32_t dB1 = aB + (r1 * SMSH + off) * 2;
    const uint32_t STo = HG_STAGE * 2;     // per-stage bytes

    // ldmatrix lane-relative offsets (bytes)
    int la = lane & 7, lg = lane >> 3;     // lg in 0..3
    uint32_t offLA = (uint32_t)(((la + (lg & 1) * 8) * SMSH + (lg >> 1) * 8) * 2);
    uint32_t offLB = (uint32_t)(((la + (lg >> 1) * 8) * SMSH + (lg & 1) * 8) * 2);
    uint32_t baseLA = aA + offLA + (uint32_t)(wr * 64 * SMSH * 2);
    uint32_t baseLB = aB + offLB + (uint32_t)(wc * 32 * SMSH * 2);

    float acc[16][4];
#pragma unroll
    for (int i = 0; i < 16; i++)
#pragma unroll
        for (int j = 0; j < 4; j++) acc[i][j] = 0.f;

    int nch = Kpad >> 5;    // 32-K chunks (nch >= 2 by contract)
    CP16(dA0, pA0); CP16(dA1, pA1); CP16(dB0, pB0); CP16(dB1, pB1);
    CPCOMMIT();
    {
        int k0 = 32;
        CP16(dA0 + STo, pA0 + k0); CP16(dA1 + STo, pA1 + k0);
        CP16(dB0 + STo, pB0 + k0); CP16(dB1 + STo, pB1 + k0);
        CPCOMMIT();
    }

    for (int ch = 0; ch < nch; ch++) {
        if (ch + 2 < nch) {
            int k0 = (ch + 2) << 5;
            uint32_t o = ((ch + 2) % 3) * STo;
            CP16(dA0 + o, pA0 + k0); CP16(dA1 + o, pA1 + k0);
            CP16(dB0 + o, pB0 + k0); CP16(dB1 + o, pB1 + k0);
            CPCOMMIT();
            cp_wait<2>();
        } else if (ch + 1 < nch) {
            cp_wait<1>();
        } else {
            cp_wait<0>();
        }
        __syncthreads();
        uint32_t stA = baseLA + (ch % 3) * STo;
        uint32_t stB = baseLB + (ch % 3) * STo;
#pragma unroll
        for (int s = 0; s < 2; s++) {
            uint32_t af[4][4], bf[4][2];
#pragma unroll
            for (int tm = 0; tm < 4; tm++)
                ldsm4(af[tm][0], af[tm][1], af[tm][2], af[tm][3],
                      stA + (uint32_t)(tm * 16 * SMSH * 2) + (uint32_t)(s * 32));
#pragma unroll
            for (int tn = 0; tn < 4; tn += 2)
                ldsm4(bf[tn][0], bf[tn][1], bf[tn + 1][0], bf[tn + 1][1],
                      stB + (uint32_t)(tn * 8 * SMSH * 2) + (uint32_t)(s * 32));
#pragma unroll
            for (int tm = 0; tm < 4; tm++)
#pragma unroll
                for (int tn = 0; tn < 4; tn++) {
                    float* c = acc[tm * 4 + tn];
                    asm volatile(
                        "mma.sync.aligned.m16n8k16.row.col.f32.f16.f16.f32 "
                        "{%0,%1,%2,%3}, {%4,%5,%6,%7}, {%8,%9}, {%0,%1,%2,%3};"
                        : "+f"(c[0]), "+f"(c[1]), "+f"(c[2]), "+f"(c[3])
                        : "r"(af[tm][0]), "r"(af[tm][1]), "r"(af[tm][2]), "r"(af[tm][3]),
                          "r"(bf[tn][0]), "r"(bf[tn][1]));
                }
        }
        __syncthreads();
    }

    // epilogue
    float thr = (EPI == 2) ? thr_p[0] : 0.f;
#pragma unroll
    for (int tm = 0; tm < 4; tm++) {
#pragma unroll
        for (int half_ = 0; half_ < 2; half_++) {
            int gr = row0 + wr * 64 + tm * 16 + q + half_ * 8;
            if (gr >= M) continue;
#pragma unroll
            for (int tn = 0; tn < 4; tn++) {
#pragma unroll
                for (int cc = 0; cc < 2; cc++) {
                    int gc = col0 + wc * 32 + tn * 8 + 2 * t4 + cc;
                    if (gc >= fillw) continue;
                    float v = 0.f;
                    if (gc < N) {
                        v = acc[tm * 4 + tn][half_ * 2 + cc];
                        if (EPI != 0) v += bias[gc];
                        if (EPI == 1) v = fmaxf(v, 0.f);
                        if (EPI == 2) { v = fmaxf(v, 0.f); v = fmaxf(v - thr, 0.f); }
                    }
                    if (OUTH) ((__half*)Cv)[(long)gr * ldc + gc] = __float2half_rn(v);
                    else      ((float*)Cv)[(long)gr * ldc + gc] = v;
                }
            }
        }
    }
}

// ---------------- fp32 SGEMM (f3 tail layer) ----------------
#define BM 128
#define BN 128
#define BK 16
#define AP 132
template <int EPI>
__global__ __launch_bounds__(256, 2) void k_sgemm(
    const float* __restrict__ A, const float* __restrict__ B,
    const float* __restrict__ bias, const float* __restrict__ thr_p,
    float* __restrict__ C, int M, int N, int K)
{
    __shared__ float As[2][BK][AP];
    __shared__ float Bs[2][BK][BN];
    int tid = threadIdx.x;
    int row0 = blockIdx.y * BM, col0 = blockIdx.x * BN;
    int tx = tid & 15, ty = tid >> 4;
    int ar[8], ac[8], br[8], bc[8];
#pragma unroll
    for (int i = 0; i < 8; i++) {
        int idx = i * 256 + tid;
        ar[i] = idx >> 4;  ac[i] = idx & 15;
        br[i] = idx >> 7;  bc[i] = idx & 127;
    }
    float acc[8][8];
#pragma unroll
    for (int i = 0; i < 8; i++)
#pragma unroll
        for (int j = 0; j < 8; j++) acc[i][j] = 0.f;
    float ldA[8], ldB[8];
    int nt = (K + BK - 1) / BK;
#pragma unroll
    for (int i = 0; i < 8; i++) {
        int gr = row0 + ar[i], gc = ac[i];
        ldA[i] = (gr < M && gc < K) ? A[(long)gr * K + gc] : 0.f;
        int hr = br[i], hc = col0 + bc[i];
        ldB[i] = (hr < K && hc < N) ? B[(long)hr * N + hc] : 0.f;
    }
#pragma unroll
    for (int i = 0; i < 8; i++) { As[0][ac[i]][ar[i]] = ldA[i]; Bs[0][br[i]][bc[i]] = ldB[i]; }
    __syncthreads();
    int cur = 0;
    for (int t = 0; t < nt; t++) {
        int kn = (t + 1) * BK;
        if (t + 1 < nt) {
#pragma unroll
            for (int i = 0; i < 8; i++) {
                int gr = row0 + ar[i], gc = kn + ac[i];
                ldA[i] = (gr < M && gc < K) ? A[(long)gr * K + gc] : 0.f;
                int hr = kn + br[i], hc = col0 + bc[i];
                ldB[i] = (hr < K && hc < N) ? B[(long)hr * N + hc] : 0.f;
            }
        }
#pragma unroll
        for (int kk = 0; kk < BK; kk++) {
            float4 a0 = *(const float4*)&As[cur][kk][ty * 8];
            float4 a1 = *(const float4*)&As[cur][kk][ty * 8 + 4];
            float4 b0 = *(const float4*)&Bs[cur][kk][tx * 8];
            float4 b1 = *(const float4*)&Bs[cur][kk][tx * 8 + 4];
            float ra[8] = {a0.x, a0.y, a0.z, a0.w, a1.x, a1.y, a1.z, a1.w};
            float rb[8] = {b0.x, b0.y, b0.z, b0.w, b1.x, b1.y, b1.z, b1.w};
#pragma unroll
            for (int i = 0; i < 8; i++)
#pragma unroll
                for (int j = 0; j < 8; j++) acc[i][j] = fmaf(ra[i], rb[j], acc[i][j]);
        }
        if (t + 1 < nt) {
            int nxt = cur ^ 1;
#pragma unroll
            for (int i = 0; i < 8; i++) { As[nxt][ac[i]][ar[i]] = ldA[i]; Bs[nxt][br[i]][bc[i]] = ldB[i]; }
            __syncthreads();
            cur = nxt;
        }
    }
    float thr = (EPI == 2) ? thr_p[0] : 0.f;
#pragma unroll
    for (int i = 0; i < 8; i++) {
        int gr = row0 + ty * 8 + i;
        if (gr >= M) continue;
#pragma unroll
        for (int j = 0; j < 8; j++) {
            int gc = col0 + tx * 8 + j;
            if (gc >= N) continue;
            float v = acc[i][j] + (bias ? bias[gc] : 0.f);
            if (EPI == 1) v = fmaxf(v, 0.f);
            if (EPI == 2) { v = fmaxf(v, 0.f); v = fmaxf(v - thr, 0.f); }
            C[(long)gr * N + gc] = v;
        }
    }
}

// ---------------- GCN gather: fp32 in (hw), fp16 out (next GEMM A) ---------
__global__ void k_gather(const float* __restrict__ hw, const float* __restrict__ bias,
                         __half* __restrict__ out, int F)
{
    int n = blockIdx.x * 4 + threadIdx.y;
    if (n >= NN) return;
    int f4 = threadIdx.x;
    int Fq = F >> 2;
    const float4* __restrict__ hw4 = (const float4*)hw;
    float d = g_dinv[n];
    float c = d * d;
    float4 sv = hw4[(long)n * Fq + f4];
    float ax = sv.x * c, ay = sv.y * c, az = sv.z * c, aw = sv.w * c;
    int s = g_rowptr[n], e = g_rowptr[n + 1];
    int i = s;
    for (; i + 4 <= e; i += 4) {
        int   c0 = g_col[i],  c1 = g_col[i + 1], c2 = g_col[i + 2], c3 = g_col[i + 3];
        float w0 = g_wgt[i],  w1 = g_wgt[i + 1], w2 = g_wgt[i + 2], w3 = g_wgt[i + 3];
        float4 v0 = hw4[(long)c0 * Fq + f4];
        float4 v1 = hw4[(long)c1 * Fq + f4];
        float4 v2 = hw4[(long)c2 * Fq + f4];
        float4 v3 = hw4[(long)c3 * Fq + f4];
        ax += w0 * v0.x + w1 * v1.x + w2 * v2.x + w3 * v3.x;
        ay += w0 * v0.y + w1 * v1.y + w2 * v2.y + w3 * v3.y;
        az += w0 * v0.z + w1 * v1.z + w2 * v2.z + w3 * v3.z;
        aw += w0 * v0.w + w1 * v1.w + w2 * v2.w + w3 * v3.w;
    }
    for (; i < e; i++) {
        int c0 = g_col[i]; float w0 = g_wgt[i];
        float4 v0 = hw4[(long)c0 * Fq + f4];
        ax += w0 * v0.x; ay += w0 * v0.y; az += w0 * v0.z; aw += w0 * v0.w;
    }
    float4 b = ((const float4*)bias)[f4];
    ax += b.x; ay += b.y; az += b.z; aw += b.w;
    ax = ax > 0.f ? ax : expm1f(ax);
    ay = ay > 0.f ? ay : expm1f(ay);
    az = az > 0.f ? az : expm1f(az);
    aw = aw > 0.f ? aw : expm1f(aw);
    __half2 h01 = __floats2half2_rn(ax, ay);
    __half2 h23 = __floats2half2_rn(az, aw);
    __half2* o2 = (__half2*)(out + (long)n * F + f4 * 4);
    o2[0] = h01; o2[1] = h23;
}

// ---------------- pair readout: fp16 in/out ----------------
__global__ void k_pair(const __half* __restrict__ h,
                       const int* __restrict__ i1, const int* __restrict__ i2,
                       __half* __restrict__ xc)
{
    int p = blockIdx.x;
    int f = threadIdx.x;
    float v = (f < 128) ? __half2float(h[(long)i1[p] * 128 + f])
                        : __half2float(h[(long)i2[p] * 128 + (f - 128)]);
    __shared__ float red[256];
    red[f] = v * v;
    __syncthreads();
    for (int off = 128; off > 0; off >>= 1) {
        if (f < off) red[f] += red[f + off];
        __syncthreads();
    }
    float norm = fmaxf(sqrtf(red[0]), 1e-12f);
    xc[(long)p * 256 + f] = __float2half_rn(v / norm);
}

__global__ void k_out(const float* __restrict__ x, const float* __restrict__ W,
                      const float* __restrict__ b, float* __restrict__ out)
{
    int idx = blockIdx.x * blockDim.x + threadIdx.x;
    if (idx >= NB * 2) return;
    int p = idx >> 1, c = idx & 1;
    float acc = b[c];
#pragma unroll
    for (int k = 0; k < 64; k++) acc += x[p * 64 + k] * W[k * 2 + c];
    out[idx] = acc;
}

// ---------------- launch ----------------
extern "C" void kernel_launch(void* const* d_in, const int* in_sizes, int n_in,
                              void* d_out, int out_size)
{
    const float* cid   = (const float*)d_in[0];
    const int*   edges = (const int*)  d_in[1];
    const int*   i1    = (const int*)  d_in[2];
    const int*   i2    = (const int*)  d_in[3];
    const float* thr   = (const float*)d_in[4];
    const float* bb2W  = (const float*)d_in[5];  const float* bb2b = (const float*)d_in[6];
    const float* bb3W  = (const float*)d_in[7];  const float* bb3b = (const float*)d_in[8];
    const float* g1W   = (const float*)d_in[9];  const float* g1b  = (const float*)d_in[10];
    const float* g2W   = (const float*)d_in[11]; const float* g2b  = (const float*)d_in[12];
    const float* g3W   = (const float*)d_in[13]; const float* g3b  = (const float*)d_in[14];
    const float* g4W   = (const float*)d_in[15]; const float* g4b  = (const float*)d_in[16];
    const float* g5W   = (const float*)d_in[17]; const float* g5b  = (const float*)d_in[18];
    const float* f1W   = (const float*)d_in[19]; const float* f1b  = (const float*)d_in[20];
    const float* f2W   = (const float*)d_in[21]; const float* f2b  = (const float*)d_in[22];
    const float* f3W   = (const float*)d_in[23]; const float* f3b  = (const float*)d_in[24];
    const float* oW    = (const float*)d_in[25]; const float* ob   = (const float*)d_in[26];

    void *pcid, *px1, *px, *ph, *phw, *ppc, *pf1, *pf2, *pf3, *pwt;
    cudaGetSymbolAddress(&pcid, g_cid);
    cudaGetSymbolAddress(&px1,  g_x1);
    cudaGetSymbolAddress(&px,   g_x);
    cudaGetSymbolAddress(&ph,   g_h);
    cudaGetSymbolAddress(&phw,  g_hw);
    cudaGetSymbolAddress(&ppc,  g_pc);
    cudaGetSymbolAddress(&pf1,  g_f1);
    cudaGetSymbolAddress(&pf2,  g_f2);
    cudaGetSymbolAddress(&pf3,  g_f3);
    cudaGetSymbolAddress(&pwt,  g_wt);
    __half* cidp = (__half*)pcid;
    __half* x1   = (__half*)px1;
    __half* x    = (__half*)px;
    __half* h    = (__half*)ph;
    float*  hw   = (float*)phw;
    __half* pc   = (__half*)ppc;
    __half* f1o  = (__half*)pf1;
    float*  f2o  = (float*)pf2;
    float*  f3o  = (float*)pf3;
    __half* wt   = (__half*)pwt;

    // one-time stream/event setup (first call is the eager correctness run)
    static cudaStream_t s2 = nullptr;
    static cudaEvent_t evF = nullptr, evJ = nullptr;
    if (!s2) {
        cudaStreamCreateWithFlags(&s2, cudaStreamNonBlocking);
        cudaEventCreateWithFlags(&evF, cudaEventDisableTiming);
        cudaEventCreateWithFlags(&evJ, cudaEventDisableTiming);
        cudaFuncSetAttribute(k_hgemm<2,1>, cudaFuncAttributeMaxDynamicSharedMemorySize, HG_SMEM);
        cudaFuncSetAttribute(k_hgemm<1,1>, cudaFuncAttributeMaxDynamicSharedMemorySize, HG_SMEM);
        cudaFuncSetAttribute(k_hgemm<0,0>, cudaFuncAttributeMaxDynamicSharedMemorySize, HG_SMEM);
        cudaFuncSetAttribute(k_hgemm<1,0>, cudaFuncAttributeMaxDynamicSharedMemorySize, HG_SMEM);
    }

    int MY = NNP / 128;  // 235
    dim3 tb(32, 8);

    // fork point for side stream
    cudaEventRecord(evF, 0);

    // --- main stream: BasicBlock critical path ---
    k_pad_cid<<<(NNP * 896 + 255) / 256, 256>>>(cid);
    k_transposeP<<<dim3(28, 28), tb>>>(bb2W, wt + OFF_BB2, 881, 881, 896, 896, 896);
    k_transposeP<<<dim3(8, 28),  tb>>>(bb3W, wt + OFF_BB3, 881, 256, 896, 896, 256);
    k_hgemm<2,1><<<dim3(7, MY), 256, HG_SMEM>>>(cidp, wt + OFF_BB2, bb2b, thr, x1,
                                                NN, 881, 896, 896, 896, 896, 896);
    k_hgemm<1,1><<<dim3(2, MY), 256, HG_SMEM>>>(x1, wt + OFF_BB3, bb3b, nullptr, x,
                                                NN, 256, 896, 896, 896, 256, 256);

    // --- side stream: graph preprocessing + remaining transposes (overlaps BB GEMMs) ---
    cudaStreamWaitEvent(s2, evF, 0);
    k_zero_deg<<<(NN + 255) / 256, 256, 0, s2>>>();
    k_count<<<(NE + 255) / 256, 256, 0, s2>>>(edges);
    k_dinv<<<(NN + 255) / 256, 256, 0, s2>>>();
    k_scanA<<<NSB, 256, 0, s2>>>();
    k_scanB<<<1, 128, 0, s2>>>();
    k_scanC<<<NSB, 256, 0, s2>>>();
    k_fill<<<(NE + 255) / 256, 256, 0, s2>>>(edges);
    k_transposeP<<<dim3(8, 8),  tb, 0, s2>>>(g1W,  wt + OFF_G1,  256, 256, 256, 256, 256);
    k_transposeP<<<dim3(8, 8),  tb, 0, s2>>>(g2W,  wt + OFF_G2,  256, 256, 256, 256, 256);
    k_transposeP<<<dim3(8, 8),  tb, 0, s2>>>(g3W,  wt + OFF_G3,  256, 256, 256, 256, 256);
    k_transposeP<<<dim3(4, 8),  tb, 0, s2>>>(g4W,  wt + OFF_G4,  256, 128, 256, 256, 128);
    k_transposeP<<<dim3(4, 4),  tb, 0, s2>>>(g5W,  wt + OFF_G5,  128, 128, 128, 128, 128);
    k_transposeP<<<dim3(32, 8), tb, 0, s2>>>(f1W,  wt + OFF_F1,  256, 1024, 256, 256, 1024);
    k_transposeP<<<dim3(8, 32), tb, 0, s2>>>(f2W,  wt + OFF_F2,  1024, 256, 1024, 1024, 256);
    cudaEventRecord(evJ, s2);

    // join before GCN section (needs graph CSR + GCN/F weights)
    cudaStreamWaitEvent(0, evJ, 0);

    // --- GCN layers (GEMM -> fp32 hw -> gather -> fp16) ---
    dim3 gat256(64, 4), gat128(32, 4);
    int  ngb = (NN + 3) / 4;
    k_hgemm<0,0><<<dim3(2, MY), 256, HG_SMEM>>>(x, wt + OFF_G1, nullptr, nullptr, hw,
                                                NN, 256, 256, 256, 256, 256, 256);
    k_gather<<<ngb, gat256>>>(hw, g1b, h, 256);
    k_hgemm<0,0><<<dim3(2, MY), 256, HG_SMEM>>>(h, wt + OFF_G2, nullptr, nullptr, hw,
                                                NN, 256, 256, 256, 256, 256, 256);
    k_gather<<<ngb, gat256>>>(hw, g2b, x, 256);
    k_hgemm<0,0><<<dim3(2, MY), 256, HG_SMEM>>>(x, wt + OFF_G3, nullptr, nullptr, hw,
                                                NN, 256, 256, 256, 256, 256, 256);
    k_gather<<<ngb, gat256>>>(hw, g3b, h, 256);
    k_hgemm<0,0><<<dim3(1, MY), 256, HG_SMEM>>>(h, wt + OFF_G4, nullptr, nullptr, hw,
                                                NN, 128, 256, 256, 256, 128, 128);
    k_gather<<<ngb, gat128>>>(hw, g4b, x, 128);
    k_hgemm<0,0><<<dim3(1, MY), 256, HG_SMEM>>>(x, wt + OFF_G5, nullptr, nullptr, hw,
                                                NN, 128, 128, 128, 128, 128, 128);
    k_gather<<<ngb, gat128>>>(hw, g5b, h, 128);

    // --- pair readout ---
    k_pair<<<NB, 256>>>(h, i1, i2, pc);
    k_hgemm<1,1><<<dim3(8, 32), 256, HG_SMEM>>>(pc,  wt + OFF_F1, f1b, nullptr, f1o,
                                                NB, 1024, 256, 256, 256, 1024, 1024);
    k_hgemm<1,0><<<dim3(2, 32), 256, HG_SMEM>>>(f1o, wt + OFF_F2, f2b, nullptr, f2o,
                                                NB, 256, 1024, 1024, 1024, 256, 256);
    k_sgemm<1><<<dim3(1, 32), 256>>>(f2o, f3W, f3b, nullptr, f3o, NB, 64, 256);
    k_out<<<(NB * 2 + 255) / 256, 256>>>(f3o, oW, ob, (float*)d_out);
}

// round 14
// speedup vs baseline: 1.1201x; 1.0334x over previous
#include <cuda_runtime.h>
#include <cuda_fp16.h>
#include <math.h>
#include <stdint.h>

#define NN 30000
#define NNP 30080   // padded to multiple of 128
#define NE 480000
#define NB 4096
#define NSB 118

// ---------------- device scratch ----------------
__device__ __align__(16) __half g_cid[NNP * 896];
__device__ __align__(16) __half g_x1[NNP * 896];
__device__ __align__(16) __half g_x [NNP * 256];
__device__ __align__(16) __half g_h [NNP * 256];
__device__ float g_hw[NNP * 256];          // GEMM out / gather in (fp32)
__device__ __align__(16) __half g_pc[NB * 256];    // pair out
__device__ __align__(16) __half g_f1[NB * 1024];   // f1 out
__device__ float g_f2[NB * 256];           // f2 out (feeds fp32 sgemm)
__device__ float g_f3[NB * 64];            // f3 out
__device__ float g_dinv[NN];
__device__ int   g_deg[NN];
__device__ int   g_cnt[NN];
__device__ int   g_rowptr[NN + 1];
__device__ int   g_col[NE];
__device__ float g_wgt[NE];
__device__ int   g_bsum[128];
__device__ int   g_boff[128];

// transposed fp16 weights (element offsets)
#define OFF_BB2 0                       // 896 x 896
#define OFF_BB3 (OFF_BB2 + 896*896)     // 256 x 896
#define OFF_G1  (OFF_BB3 + 256*896)     // 256 x 256
#define OFF_G2  (OFF_G1  + 256*256)
#define OFF_G3  (OFF_G2  + 256*256)
#define OFF_G4  (OFF_G3  + 256*256)    // 128 x 256
#define OFF_G5  (OFF_G4  + 128*256)    // 128 x 128
#define OFF_F1  (OFF_G5  + 128*128)    // 1024 x 256
#define OFF_F2  (OFF_F1  + 1024*256)   // 256 x 1024
#define WT_TOT  (OFF_F2  + 256*1024)
__device__ __align__(16) __half g_wt[WT_TOT];

// ---------------- helpers ----------------
__device__ __forceinline__ uint32_t smem_u32(const void* p) {
    uint32_t a;
    asm("{ .reg .u64 t; cvta.to.shared.u64 t, %1; cvt.u32.u64 %0, t; }" : "=r"(a) : "l"(p));
    return a;
}
__device__ __forceinline__ void ldsm4(uint32_t& r0, uint32_t& r1, uint32_t& r2, uint32_t& r3,
                                      uint32_t addr) {
    asm volatile("ldmatrix.sync.aligned.m8n8.x4.shared.b16 {%0,%1,%2,%3}, [%4];"
                 : "=r"(r0), "=r"(r1), "=r"(r2), "=r"(r3) : "r"(addr));
}
#define CP16(d, s) asm volatile("cp.async.cg.shared.global [%0], [%1], 16;" :: "r"(d), "l"(s) : "memory")
#define CPCOMMIT() asm volatile("cp.async.commit_group;" ::: "memory")
template<int W> __device__ __forceinline__ void cp_wait() {
    asm volatile("cp.async.wait_group %0;" :: "n"(W) : "memory");
}

// ---------------- graph preprocessing ----------------
__global__ void k_zero_deg() {
    int i = blockIdx.x * blockDim.x + threadIdx.x;
    if (i < NN) { g_deg[i] = 0; g_cnt[i] = 0; }
}
__global__ void k_count(const int* __restrict__ edges) {
    int e = blockIdx.x * blockDim.x + threadIdx.x;
    if (e < NE) atomicAdd(&g_deg[edges[NE + e]], 1);
}
__global__ void k_dinv() {
    int i = blockIdx.x * blockDim.x + threadIdx.x;
    if (i < NN) g_dinv[i] = rsqrtf((float)(g_deg[i] + 1));
}
__global__ void k_scanA() {
    __shared__ int sh[256];
    int tid = threadIdx.x;
    int i = blockIdx.x * 256 + tid;
    int v = (i < NN) ? g_deg[i] : 0;
    sh[tid] = v;
    __syncthreads();
#pragma unroll
    for (int off = 1; off < 256; off <<= 1) {
        int t = (tid >= off) ? sh[tid - off] : 0;
        __syncthreads();
        sh[tid] += t;
        __syncthreads();
    }
    if (i < NN) g_rowptr[i] = sh[tid] - v;
    if (tid == 255) g_bsum[blockIdx.x] = sh[255];
}
__global__ void k_scanB() {
    __shared__ int sh[128];
    int tid = threadIdx.x;
    int v = (tid < NSB) ? g_bsum[tid] : 0;
    sh[tid] = v;
    __syncthreads();
#pragma unroll
    for (int off = 1; off < 128; off <<= 1) {
        int t = (tid >= off) ? sh[tid - off] : 0;
        __syncthreads();
        sh[tid] += t;
        __syncthreads();
    }
    if (tid < NSB) g_boff[tid] = sh[tid] - v;
    if (tid == 127) g_rowptr[NN] = sh[127];
}
__global__ void k_scanC() {
    int i = blockIdx.x * 256 + threadIdx.x;
    if (i < NN) g_rowptr[i] += g_boff[blockIdx.x];
}
__global__ void k_fill(const int* __restrict__ edges) {
    int e = blockIdx.x * blockDim.x + threadIdx.x;
    if (e < NE) {
        int s = edges[e];
        int d = edges[NE + e];
        int pos = g_rowptr[d] + atomicAdd(&g_cnt[d], 1);
        g_col[pos] = s;
        g_wgt[pos] = g_dinv[s] * g_dinv[d];
    }
}

// ---------------- producers: pad + fp16-convert ----------------
__global__ void k_pad_cid(const float* __restrict__ cid) {
    int idx = blockIdx.x * 256 + threadIdx.x;
    if (idx >= NNP * 896) return;
    int row = idx / 896, col = idx - row * 896;
    g_cid[idx] = __float2half_rn((row < NN && col < 881) ? cid[(long)row * 881 + col] : 0.f);
}
// dst[c*dld + r] = fp16(src[r*C + c]); writes full padded region [Cp rows x Rp cols], zeros outside
__global__ void k_transposeP(const float* __restrict__ src, __half* __restrict__ dst,
                             int R, int C, int dld, int Rp, int Cp) {
    __shared__ float t[32][33];
    int c0 = blockIdx.x * 32, r0 = blockIdx.y * 32;
    int x = threadIdx.x, y = threadIdx.y;  // 32 x 8
#pragma unroll
    for (int i = 0; i < 4; i++) {
        int r = r0 + y + i * 8;
        t[y + i * 8][x] = (r < R && c0 + x < C) ? src[(long)r * C + c0 + x] : 0.f;
    }
    __syncthreads();
#pragma unroll
    for (int i = 0; i < 4; i++) {
        int c = c0 + y + i * 8;
        if (c < Cp && r0 + x < Rp) dst[(long)c * dld + r0 + x] = __float2half_rn(t[x][y + i * 8]);
    }
}

// ---------------- fp16 mma.sync GEMM, cp.async 3-stage, ldmatrix frags -----
// C[M,N] = A[M,Kpad] @ Bt[N,Kpad]^T, fp16 operands, fp32 accum.
// EPI: 0 none, 1 relu+bias, 2 relu+softthr+bias. OUTH: 1 -> half out, 0 -> float.
// Requires Kpad multiple of 32 and Kpad >= 64 (nch >= 2).
#define SMSH 40   // smem row stride in halfs (32 data + 8 pad)
#define HG_STAGE (128 * SMSH)              // halfs per operand per stage
#define HG_SMEM  (3 * HG_STAGE * 2 * 2)    // bytes: 3 stages x (A+B)
template <int EPI, int OUTH>
__global__ __launch_bounds__(256, 2) void k_hgemm(
    const __half* __restrict__ A, const __half* __restrict__ Bt,
    const float* __restrict__ bias, const float* __restrict__ thr_p,
    void* __restrict__ Cv, int M, int N, int Kpad, int lda, int ldb, int ldc, int fillw)
{
    extern __shared__ __align__(16) __half sm[];
    __half* smA = sm;                      // 3 x HG_STAGE
    __half* smB = sm + 3 * HG_STAGE;       // 3 x HG_STAGE
    int tid = threadIdx.x, wid = tid >> 5, lane = tid & 31;
    int row0 = blockIdx.y * 128, col0 = blockIdx.x * 128;
    int wr = wid >> 2, wc = wid & 3;       // warp grid 2 x 4, warp tile 64 x 32
    int q = lane >> 2, t4 = lane & 3;

    int r0 = tid >> 2, off = (tid & 3) * 8;   // cp.async coords (halfs)
    int r1 = r0 + 64;
    const __half* pA0 = A + (long)(row0 + r0) * lda + off;
    const __half* pA1 = A + (long)(row0 + r1) * lda + off;
    const __half* pB0 = Bt + (long)(col0 + r0) * ldb + off;
    const __half* pB1 = Bt + (long)(col0 + r1) * ldb + off;
    uint32_t aA = smem_u32(smA), aB = smem_u32(smB);
    uint32_t dA0 = aA + (r0 * SMSH + off) * 2;
    uint32_t dA1 = aA + (r1 * SMSH + off) * 2;
    uint32_t dB0 = aB + (r0 * SMSH + off) * 2;
    uint32_t dB1 = aB + (r1 * SMSH + off) * 2;
    const uint32_t STo = HG_STAGE * 2;     // per-stage bytes

    // ldmatrix lane-relative offsets (bytes)
    int la = lane & 7, lg = lane >> 3;     // lg in 0..3
    uint32_t offLA = (uint32_t)(((la + (lg & 1) * 8) * SMSH + (lg >> 1) * 8) * 2);
    uint32_t offLB = (uint32_t)(((la + (lg >> 1) * 8) * SMSH + (lg & 1) * 8) * 2);
    uint32_t baseLA = aA + offLA + (uint32_t)(wr * 64 * SMSH * 2);
    uint32_t baseLB = aB + offLB + (uint32_t)(wc * 32 * SMSH * 2);

    float acc[16][4];
#pragma unroll
    for (int i = 0; i < 16; i++)
#pragma unroll
        for (int j = 0; j < 4; j++) acc[i][j] = 0.f;

    int nch = Kpad >> 5;    // 32-K chunks (nch >= 2 by contract)
    CP16(dA0, pA0); CP16(dA1, pA1); CP16(dB0, pB0); CP16(dB1, pB1);
    CPCOMMIT();
    {
        int k0 = 32;
        CP16(dA0 + STo, pA0 + k0); CP16(dA1 + STo, pA1 + k0);
        CP16(dB0 + STo, pB0 + k0); CP16(dB1 + STo, pB1 + k0);
        CPCOMMIT();
    }

    for (int ch = 0; ch < nch; ch++) {
        if (ch + 2 < nch) {
            int k0 = (ch + 2) << 5;
            uint32_t o = ((ch + 2) % 3) * STo;
            CP16(dA0 + o, pA0 + k0); CP16(dA1 + o, pA1 + k0);
            CP16(dB0 + o, pB0 + k0); CP16(dB1 + o, pB1 + k0);
            CPCOMMIT();
            cp_wait<2>();
        } else if (ch + 1 < nch) {
            cp_wait<1>();
        } else {
            cp_wait<0>();
        }
        // single barrier per chunk: bounds warp skew to <1 iteration; with 3
        // stages the prefetch target (ch+2)%3 never aliases the read stage ch%3
        __syncthreads();
        uint32_t stA = baseLA + (ch % 3) * STo;
        uint32_t stB = baseLB + (ch % 3) * STo;
#pragma unroll
        for (int s = 0; s < 2; s++) {
            uint32_t af[4][4], bf[4][2];
#pragma unroll
            for (int tm = 0; tm < 4; tm++)
                ldsm4(af[tm][0], af[tm][1], af[tm][2], af[tm][3],
                      stA + (uint32_t)(tm * 16 * SMSH * 2) + (uint32_t)(s * 32));
#pragma unroll
            for (int tn = 0; tn < 4; tn += 2)
                ldsm4(bf[tn][0], bf[tn][1], bf[tn + 1][0], bf[tn + 1][1],
                      stB + (uint32_t)(tn * 8 * SMSH * 2) + (uint32_t)(s * 32));
#pragma unroll
            for (int tm = 0; tm < 4; tm++)
#pragma unroll
                for (int tn = 0; tn < 4; tn++) {
                    float* c = acc[tm * 4 + tn];
                    asm volatile(
                        "mma.sync.aligned.m16n8k16.row.col.f32.f16.f16.f32 "
                        "{%0,%1,%2,%3}, {%4,%5,%6,%7}, {%8,%9}, {%0,%1,%2,%3};"
                        : "+f"(c[0]), "+f"(c[1]), "+f"(c[2]), "+f"(c[3])
                        : "r"(af[tm][0]), "r"(af[tm][1]), "r"(af[tm][2]), "r"(af[tm][3]),
                          "r"(bf[tn][0]), "r"(bf[tn][1]));
                }
        }
    }

    // epilogue
    float thr = (EPI == 2) ? thr_p[0] : 0.f;
#pragma unroll
    for (int tm = 0; tm < 4; tm++) {
#pragma unroll
        for (int half_ = 0; half_ < 2; half_++) {
            int gr = row0 + wr * 64 + tm * 16 + q + half_ * 8;
            if (gr >= M) continue;
#pragma unroll
            for (int tn = 0; tn < 4; tn++) {
#pragma unroll
                for (int cc = 0; cc < 2; cc++) {
                    int gc = col0 + wc * 32 + tn * 8 + 2 * t4 + cc;
                    if (gc >= fillw) continue;
                    float v = 0.f;
                    if (gc < N) {
                        v = acc[tm * 4 + tn][half_ * 2 + cc];
                        if (EPI != 0) v += bias[gc];
                        if (EPI == 1) v = fmaxf(v, 0.f);
                        if (EPI == 2) { v = fmaxf(v, 0.f); v = fmaxf(v - thr, 0.f); }
                    }
                    if (OUTH) ((__half*)Cv)[(long)gr * ldc + gc] = __float2half_rn(v);
                    else      ((float*)Cv)[(long)gr * ldc + gc] = v;
                }
            }
        }
    }
}

// ---------------- fp32 SGEMM (f3 tail layer) ----------------
#define BM 128
#define BN 128
#define BK 16
#define AP 132
template <int EPI>
__global__ __launch_bounds__(256, 2) void k_sgemm(
    const float* __restrict__ A, const float* __restrict__ B,
    const float* __restrict__ bias, const float* __restrict__ thr_p,
    float* __restrict__ C, int M, int N, int K)
{
    __shared__ float As[2][BK][AP];
    __shared__ float Bs[2][BK][BN];
    int tid = threadIdx.x;
    int row0 = blockIdx.y * BM, col0 = blockIdx.x * BN;
    int tx = tid & 15, ty = tid >> 4;
    int ar[8], ac[8], br[8], bc[8];
#pragma unroll
    for (int i = 0; i < 8; i++) {
        int idx = i * 256 + tid;
        ar[i] = idx >> 4;  ac[i] = idx & 15;
        br[i] = idx >> 7;  bc[i] = idx & 127;
    }
    float acc[8][8];
#pragma unroll
    for (int i = 0; i < 8; i++)
#pragma unroll
        for (int j = 0; j < 8; j++) acc[i][j] = 0.f;
    float ldA[8], ldB[8];
    int nt = (K + BK - 1) / BK;
#pragma unroll
    for (int i = 0; i < 8; i++) {
        int gr = row0 + ar[i], gc = ac[i];
        ldA[i] = (gr < M && gc < K) ? A[(long)gr * K + gc] : 0.f;
        int hr = br[i], hc = col0 + bc[i];
        ldB[i] = (hr < K && hc < N) ? B[(long)hr * N + hc] : 0.f;
    }
#pragma unroll
    for (int i = 0; i < 8; i++) { As[0][ac[i]][ar[i]] = ldA[i]; Bs[0][br[i]][bc[i]] = ldB[i]; }
    __syncthreads();
    int cur = 0;
    for (int t = 0; t < nt; t++) {
        int kn = (t + 1) * BK;
        if (t + 1 < nt) {
#pragma unroll
            for (int i = 0; i < 8; i++) {
                int gr = row0 + ar[i], gc = kn + ac[i];
                ldA[i] = (gr < M && gc < K) ? A[(long)gr * K + gc] : 0.f;
                int hr = kn + br[i], hc = col0 + bc[i];
                ldB[i] = (hr < K && hc < N) ? B[(long)hr * N + hc] : 0.f;
            }
        }
#pragma unroll
        for (int kk = 0; kk < BK; kk++) {
            float4 a0 = *(const float4*)&As[cur][kk][ty * 8];
            float4 a1 = *(const float4*)&As[cur][kk][ty * 8 + 4];
            float4 b0 = *(const float4*)&Bs[cur][kk][tx * 8];
            float4 b1 = *(const float4*)&Bs[cur][kk][tx * 8 + 4];
            float ra[8] = {a0.x, a0.y, a0.z, a0.w, a1.x, a1.y, a1.z, a1.w};
            float rb[8] = {b0.x, b0.y, b0.z, b0.w, b1.x, b1.y, b1.z, b1.w};
#pragma unroll
            for (int i = 0; i < 8; i++)
#pragma unroll
                for (int j = 0; j < 8; j++) acc[i][j] = fmaf(ra[i], rb[j], acc[i][j]);
        }
        if (t + 1 < nt) {
            int nxt = cur ^ 1;
#pragma unroll
            for (int i = 0; i < 8; i++) { As[nxt][ac[i]][ar[i]] = ldA[i]; Bs[nxt][br[i]][bc[i]] = ldB[i]; }
            __syncthreads();
            cur = nxt;
        }
    }
    float thr = (EPI == 2) ? thr_p[0] : 0.f;
#pragma unroll
    for (int i = 0; i < 8; i++) {
        int gr = row0 + ty * 8 + i;
        if (gr >= M) continue;
#pragma unroll
        for (int j = 0; j < 8; j++) {
            int gc = col0 + tx * 8 + j;
            if (gc >= N) continue;
            float v = acc[i][j] + (bias ? bias[gc] : 0.f);
            if (EPI == 1) v = fmaxf(v, 0.f);
            if (EPI == 2) { v = fmaxf(v, 0.f); v = fmaxf(v - thr, 0.f); }
            C[(long)gr * N + gc] = v;
        }
    }
}

// ---------------- GCN gather: fp32 in (hw), fp16 out (next GEMM A) ---------
// unroll x8: 8 outstanding float4 loads per thread to cover L2 latency
__global__ void k_gather(const float* __restrict__ hw, const float* __restrict__ bias,
                         __half* __restrict__ out, int F)
{
    int n = blockIdx.x * 4 + threadIdx.y;
    if (n >= NN) return;
    int f4 = threadIdx.x;
    int Fq = F >> 2;
    const float4* __restrict__ hw4 = (const float4*)hw;
    float d = g_dinv[n];
    float c = d * d;
    float4 sv = hw4[(long)n * Fq + f4];
    float ax = sv.x * c, ay = sv.y * c, az = sv.z * c, aw = sv.w * c;
    int s = g_rowptr[n], e = g_rowptr[n + 1];
    int i = s;
    for (; i + 8 <= e; i += 8) {
        int   c0 = g_col[i],     c1 = g_col[i + 1], c2 = g_col[i + 2], c3 = g_col[i + 3];
        int   c4 = g_col[i + 4], c5 = g_col[i + 5], c6 = g_col[i + 6], c7 = g_col[i + 7];
        float w0 = g_wgt[i],     w1 = g_wgt[i + 1], w2 = g_wgt[i + 2], w3 = g_wgt[i + 3];
        float w4 = g_wgt[i + 4], w5 = g_wgt[i + 5], w6 = g_wgt[i + 6], w7 = g_wgt[i + 7];
        float4 v0 = hw4[(long)c0 * Fq + f4];
        float4 v1 = hw4[(long)c1 * Fq + f4];
        float4 v2 = hw4[(long)c2 * Fq + f4];
        float4 v3 = hw4[(long)c3 * Fq + f4];
        float4 v4 = hw4[(long)c4 * Fq + f4];
        float4 v5 = hw4[(long)c5 * Fq + f4];
        float4 v6 = hw4[(long)c6 * Fq + f4];
        float4 v7 = hw4[(long)c7 * Fq + f4];
        ax += w0 * v0.x + w1 * v1.x + w2 * v2.x + w3 * v3.x
            + w4 * v4.x + w5 * v5.x + w6 * v6.x + w7 * v7.x;
        ay += w0 * v0.y + w1 * v1.y + w2 * v2.y + w3 * v3.y
            + w4 * v4.y + w5 * v5.y + w6 * v6.y + w7 * v7.y;
        az += w0 * v0.z + w1 * v1.z + w2 * v2.z + w3 * v3.z
            + w4 * v4.z + w5 * v5.z + w6 * v6.z + w7 * v7.z;
        aw += w0 * v0.w + w1 * v1.w + w2 * v2.w + w3 * v3.w
            + w4 * v4.w + w5 * v5.w + w6 * v6.w + w7 * v7.w;
    }
    for (; i + 4 <= e; i += 4) {
        int   c0 = g_col[i],  c1 = g_col[i + 1], c2 = g_col[i + 2], c3 = g_col[i + 3];
        float w0 = g_wgt[i],  w1 = g_wgt[i + 1], w2 = g_wgt[i + 2], w3 = g_wgt[i + 3];
        float4 v0 = hw4[(long)c0 * Fq + f4];
        float4 v1 = hw4[(long)c1 * Fq + f4];
        float4 v2 = hw4[(long)c2 * Fq + f4];
        float4 v3 = hw4[(long)c3 * Fq + f4];
        ax += w0 * v0.x + w1 * v1.x + w2 * v2.x + w3 * v3.x;
        ay += w0 * v0.y + w1 * v1.y + w2 * v2.y + w3 * v3.y;
        az += w0 * v0.z + w1 * v1.z + w2 * v2.z + w3 * v3.z;
        aw += w0 * v0.w + w1 * v1.w + w2 * v2.w + w3 * v3.w;
    }
    for (; i < e; i++) {
        int c0 = g_col[i]; float w0 = g_wgt[i];
        float4 v0 = hw4[(long)c0 * Fq + f4];
        ax += w0 * v0.x; ay += w0 * v0.y; az += w0 * v0.z; aw += w0 * v0.w;
    }
    float4 b = ((const float4*)bias)[f4];
    ax += b.x; ay += b.y; az += b.z; aw += b.w;
    ax = ax > 0.f ? ax : expm1f(ax);
    ay = ay > 0.f ? ay : expm1f(ay);
    az = az > 0.f ? az : expm1f(az);
    aw = aw > 0.f ? aw : expm1f(aw);
    __half2 h01 = __floats2half2_rn(ax, ay);
    __half2 h23 = __floats2half2_rn(az, aw);
    __half2* o2 = (__half2*)(out + (long)n * F + f4 * 4);
    o2[0] = h01; o2[1] = h23;
}

// ---------------- pair readout: fp16 in/out ----------------
__global__ void k_pair(const __half* __restrict__ h,
                       const int* __restrict__ i1, const int* __restrict__ i2,
                       __half* __restrict__ xc)
{
    int p = blockIdx.x;
    int f = threadIdx.x;
    float v = (f < 128) ? __half2float(h[(long)i1[p] * 128 + f])
                        : __half2float(h[(long)i2[p] * 128 + (f - 128)]);
    __shared__ float red[256];
    red[f] = v * v;
    __syncthreads();
    for (int off = 128; off > 0; off >>= 1) {
        if (f < off) red[f] += red[f + off];
        __syncthreads();
    }
    float norm = fmaxf(sqrtf(red[0]), 1e-12f);
    xc[(long)p * 256 + f] = __float2half_rn(v / norm);
}

__global__ void k_out(const float* __restrict__ x, const float* __restrict__ W,
                      const float* __restrict__ b, float* __restrict__ out)
{
    int idx = blockIdx.x * blockDim.x + threadIdx.x;
    if (idx >= NB * 2) return;
    int p = idx >> 1, c = idx & 1;
    float acc = b[c];
#pragma unroll
    for (int k = 0; k < 64; k++) acc += x[p * 64 + k] * W[k * 2 + c];
    out[idx] = acc;
}

// ---------------- launch ----------------
extern "C" void kernel_launch(void* const* d_in, const int* in_sizes, int n_in,
                              void* d_out, int out_size)
{
    const float* cid   = (const float*)d_in[0];
    const int*   edges = (const int*)  d_in[1];
    const int*   i1    = (const int*)  d_in[2];
    const int*   i2    = (const int*)  d_in[3];
    const float* thr   = (const float*)d_in[4];
    const float* bb2W  = (const float*)d_in[5];  const float* bb2b = (const float*)d_in[6];
    const float* bb3W  = (const float*)d_in[7];  const float* bb3b = (const float*)d_in[8];
    const float* g1W   = (const float*)d_in[9];  const float* g1b  = (const float*)d_in[10];
    const float* g2W   = (const float*)d_in[11]; const float* g2b  = (const float*)d_in[12];
    const float* g3W   = (const float*)d_in[13]; const float* g3b  = (const float*)d_in[14];
    const float* g4W   = (const float*)d_in[15]; const float* g4b  = (const float*)d_in[16];
    const float* g5W   = (const float*)d_in[17]; const float* g5b  = (const float*)d_in[18];
    const float* f1W   = (const float*)d_in[19]; const float* f1b  = (const float*)d_in[20];
    const float* f2W   = (const float*)d_in[21]; const float* f2b  = (const float*)d_in[22];
    const float* f3W   = (const float*)d_in[23]; const float* f3b  = (const float*)d_in[24];
    const float* oW    = (const float*)d_in[25]; const float* ob   = (const float*)d_in[26];

    void *pcid, *px1, *px, *ph, *phw, *ppc, *pf1, *pf2, *pf3, *pwt;
    cudaGetSymbolAddress(&pcid, g_cid);
    cudaGetSymbolAddress(&px1,  g_x1);
    cudaGetSymbolAddress(&px,   g_x);
    cudaGetSymbolAddress(&ph,   g_h);
    cudaGetSymbolAddress(&phw,  g_hw);
    cudaGetSymbolAddress(&ppc,  g_pc);
    cudaGetSymbolAddress(&pf1,  g_f1);
    cudaGetSymbolAddress(&pf2,  g_f2);
    cudaGetSymbolAddress(&pf3,  g_f3);
    cudaGetSymbolAddress(&pwt,  g_wt);
    __half* cidp = (__half*)pcid;
    __half* x1   = (__half*)px1;
    __half* x    = (__half*)px;
    __half* h    = (__half*)ph;
    float*  hw   = (float*)phw;
    __half* pc   = (__half*)ppc;
    __half* f1o  = (__half*)pf1;
    float*  f2o  = (float*)pf2;
    float*  f3o  = (float*)pf3;
    __half* wt   = (__half*)pwt;

    // one-time stream/event setup (first call is the eager correctness run)
    static cudaStream_t s2 = nullptr;
    static cudaEvent_t evF = nullptr, evJ = nullptr;
    if (!s2) {
        cudaStreamCreateWithFlags(&s2, cudaStreamNonBlocking);
        cudaEventCreateWithFlags(&evF, cudaEventDisableTiming);
        cudaEventCreateWithFlags(&evJ, cudaEventDisableTiming);
        cudaFuncSetAttribute(k_hgemm<2,1>, cudaFuncAttributeMaxDynamicSharedMemorySize, HG_SMEM);
        cudaFuncSetAttribute(k_hgemm<1,1>, cudaFuncAttributeMaxDynamicSharedMemorySize, HG_SMEM);
        cudaFuncSetAttribute(k_hgemm<0,0>, cudaFuncAttributeMaxDynamicSharedMemorySize, HG_SMEM);
        cudaFuncSetAttribute(k_hgemm<1,0>, cudaFuncAttributeMaxDynamicSharedMemorySize, HG_SMEM);
    }

    int MY = NNP / 128;  // 235
    dim3 tb(32, 8);

    // fork point for side stream
    cudaEventRecord(evF, 0);

    // --- main stream: BasicBlock critical path ---
    k_pad_cid<<<(NNP * 896 + 255) / 256, 256>>>(cid);
    k_transposeP<<<dim3(28, 28), tb>>>(bb2W, wt + OFF_BB2, 881, 881, 896, 896, 896);
    k_transposeP<<<dim3(8, 28),  tb>>>(bb3W, wt + OFF_BB3, 881, 256, 896, 896, 256);
    k_hgemm<2,1><<<dim3(7, MY), 256, HG_SMEM>>>(cidp, wt + OFF_BB2, bb2b, thr, x1,
                                                NN, 881, 896, 896, 896, 896, 896);
    k_hgemm<1,1><<<dim3(2, MY), 256, HG_SMEM>>>(x1, wt + OFF_BB3, bb3b, nullptr, x,
                                                NN, 256, 896, 896, 896, 256, 256);

    // --- side stream: graph preprocessing + remaining transposes (overlaps BB GEMMs) ---
    cudaStreamWaitEvent(s2, evF, 0);
    k_zero_deg<<<(NN + 255) / 256, 256, 0, s2>>>();
    k_count<<<(NE + 255) / 256, 256, 0, s2>>>(edges);
    k_dinv<<<(NN + 255) / 256, 256, 0, s2>>>();
    k_scanA<<<NSB, 256, 0, s2>>>();
    k_scanB<<<1, 128, 0, s2>>>();
    k_scanC<<<NSB, 256, 0, s2>>>();
    k_fill<<<(NE + 255) / 256, 256, 0, s2>>>(edges);
    k_transposeP<<<dim3(8, 8),  tb, 0, s2>>>(g1W,  wt + OFF_G1,  256, 256, 256, 256, 256);
    k_transposeP<<<dim3(8, 8),  tb, 0, s2>>>(g2W,  wt + OFF_G2,  256, 256, 256, 256, 256);
    k_transposeP<<<dim3(8, 8),  tb, 0, s2>>>(g3W,  wt + OFF_G3,  256, 256, 256, 256, 256);
    k_transposeP<<<dim3(4, 8),  tb, 0, s2>>>(g4W,  wt + OFF_G4,  256, 128, 256, 256, 128);
    k_transposeP<<<dim3(4, 4),  tb, 0, s2>>>(g5W,  wt + OFF_G5,  128, 128, 128, 128, 128);
    k_transposeP<<<dim3(32, 8), tb, 0, s2>>>(f1W,  wt + OFF_F1,  256, 1024, 256, 256, 1024);
    k_transposeP<<<dim3(8, 32), tb, 0, s2>>>(f2W,  wt + OFF_F2,  1024, 256, 1024, 1024, 256);
    cudaEventRecord(evJ, s2);

    // join before GCN section (needs graph CSR + GCN/F weights)
    cudaStreamWaitEvent(0, evJ, 0);

    // --- GCN layers (GEMM -> fp32 hw -> gather -> fp16) ---
    dim3 gat256(64, 4), gat128(32, 4);
    int  ngb = (NN + 3) / 4;
    k_hgemm<0,0><<<dim3(2, MY), 256, HG_SMEM>>>(x, wt + OFF_G1, nullptr, nullptr, hw,
                                                NN, 256, 256, 256, 256, 256, 256);
    k_gather<<<ngb, gat256>>>(hw, g1b, h, 256);
    k_hgemm<0,0><<<dim3(2, MY), 256, HG_SMEM>>>(h, wt + OFF_G2, nullptr, nullptr, hw,
                                                NN, 256, 256, 256, 256, 256, 256);
    k_gather<<<ngb, gat256>>>(hw, g2b, x, 256);
    k_hgemm<0,0><<<dim3(2, MY), 256, HG_SMEM>>>(x, wt + OFF_G3, nullptr, nullptr, hw,
                                                NN, 256, 256, 256, 256, 256, 256);
    k_gather<<<ngb, gat256>>>(hw, g3b, h, 256);
    k_hgemm<0,0><<<dim3(1, MY), 256, HG_SMEM>>>(h, wt + OFF_G4, nullptr, nullptr, hw,
                                                NN, 128, 256, 256, 256, 128, 128);
    k_gather<<<ngb, gat128>>>(hw, g4b, x, 128);
    k_hgemm<0,0><<<dim3(1, MY), 256, HG_SMEM>>>(x, wt + OFF_G5, nullptr, nullptr, hw,
                                                NN, 128, 128, 128, 128, 128, 128);
    k_gather<<<ngb, gat128>>>(hw, g5b, h, 128);

    // --- pair readout ---
    k_pair<<<NB, 256>>>(h, i1, i2, pc);
    k_hgemm<1,1><<<dim3(8, 32), 256, HG_SMEM>>>(pc,  wt + OFF_F1, f1b, nullptr, f1o,
                                                NB, 1024, 256, 256, 256, 1024, 1024);
    k_hgemm<1,0><<<dim3(2, 32), 256, HG_SMEM>>>(f1o, wt + OFF_F2, f2b, nullptr, f2o,
                                                NB, 256, 1024, 1024, 1024, 256, 256);
    k_sgemm<1><<<dim3(1, 32), 256>>>(f2o, f3W, f3b, nullptr, f3o, NB, 64, 256);
    k_out<<<(NB * 2 + 255) / 256, 256>>>(f3o, oW, ob, (float*)d_out);
}